// round 10
// baseline (speedup 1.0000x reference)
#include <cuda_runtime.h>
#include <cuda_fp16.h>
#include <cstdint>
#include <cstdio>

#define DIMB   25
#define NNODES 20000
#define NFEAT  300
#define KPAD1  320            // NFEAT padded to multiple of 32
#define NHID   64
#define NCLASS 50
#define NC2    52             // NCLASS padded to 52
#define HCAT   (DIMB * NHID)  // 1600
#define NW2    (DIMB * NC2)   // 1300
#define EDGES  320000
#define BTOT   (DIMB * NNODES)
#define SCAN_BLKS ((BTOT + 1023) / 1024)

// ---------------- scratch (static device memory; no allocs allowed) ----------
__device__ __half g_xh  [(size_t)NNODES * KPAD1];
__device__ __half g_w1h [(size_t)HCAT * KPAD1];
__device__ __half g_w2h [(size_t)NW2 * HCAT];
__device__ __half g_sup1[(size_t)NNODES * HCAT];
__device__ __half g_h1h [(size_t)NNODES * HCAT];
__device__ __half g_sup2[(size_t)NNODES * NW2];
// CSR build
__device__ int   g_cnt   [BTOT];
__device__ int   g_rowptr[BTOT + 1];
__device__ int   g_bsum  [1024];
__device__ int2  g_ecv   [(size_t)DIMB * EDGES];

// ---------------- helpers ----------------------------------------------------
__device__ __forceinline__ void mma_f16(float& c0, float& c1, float& c2, float& c3,
                                        uint32_t a0, uint32_t a1, uint32_t a2, uint32_t a3,
                                        uint32_t b0, uint32_t b1) {
    asm volatile("mma.sync.aligned.m16n8k16.row.col.f32.f16.f16.f32 "
                 "{%0,%1,%2,%3}, {%4,%5,%6,%7}, {%8,%9}, {%0,%1,%2,%3};"
                 : "+f"(c0), "+f"(c1), "+f"(c2), "+f"(c3)
                 : "r"(a0), "r"(a1), "r"(a2), "r"(a3), "r"(b0), "r"(b1));
}

__device__ __forceinline__ void ldm_x4(uint32_t& r0, uint32_t& r1,
                                       uint32_t& r2, uint32_t& r3, const void* p) {
    uint32_t addr = (uint32_t)__cvta_generic_to_shared(p);
    asm volatile("ldmatrix.sync.aligned.m8n8.x4.shared.b16 {%0,%1,%2,%3}, [%4];"
                 : "=r"(r0), "=r"(r1), "=r"(r2), "=r"(r3) : "r"(addr));
}

// ================= prep ======================================================
__global__ void cvt_x_kernel(const float* __restrict__ x, __half* __restrict__ xh) {
    size_t i = (size_t)blockIdx.x * blockDim.x + threadIdx.x;
    if (i >= (size_t)NNODES * KPAD1 / 4) return;
    int n   = (int)(i / (KPAD1 / 4));
    int col = ((int)(i % (KPAD1 / 4))) * 4;
    __half2 lo = __floats2half2_rn(0.f, 0.f), hi = lo;
    if (col < NFEAT) {
        float4 v = *(const float4*)(x + (size_t)n * NFEAT + col);
        lo = __floats2half2_rn(v.x, v.y);
        hi = __floats2half2_rn(v.z, v.w);
    }
    *(uint2*)(xh + i * 4) = make_uint2(*(uint32_t*)&lo, *(uint32_t*)&hi);
}

__global__ void repack1_kernel(const float* __restrict__ W1, __half* __restrict__ B1) {
    int i = blockIdx.x * blockDim.x + threadIdx.x;
    if (i >= HCAT * KPAD1) return;
    int n = i / KPAD1, k = i - n * KPAD1;
    int d = n >> 6, h = n & 63;
    B1[i] = (k < NFEAT) ? __float2half_rn(W1[((size_t)d * NFEAT + k) * NHID + h])
                        : __float2half_rn(0.f);
}

__global__ void repack2_kernel(const float* __restrict__ W2, __half* __restrict__ B2) {
    int i = blockIdx.x * blockDim.x + threadIdx.x;
    if (i >= NW2 * HCAT) return;
    int n = i / HCAT, k = i - n * HCAT;
    int d = n / NC2, c = n - d * NC2;
    B2[i] = (c < NCLASS) ? __float2half_rn(W2[((size_t)d * HCAT + k) * NCLASS + c])
                         : __float2half_rn(0.f);
}

// ================= fp16 tensor-core GEMM =====================================
// C (NNODES x NTOT, fp16) = A (NNODES x KPAD) * Bt (NTOT x KPAD)^T.
// BM=BN=128, BK=32, 2-stage SMEM double buffer (one barrier per tile),
// ldmatrix fragment loads, register LDG prefetch. 2 CTAs/SM.
template <int KPAD, int NTOT>
__global__ void __launch_bounds__(256, 2)
h_mma_kernel(const __half* __restrict__ A, const __half* __restrict__ Bt,
             __half* __restrict__ C) {
    constexpr int BK = 32;
    constexpr int KT = KPAD / BK;
    __shared__ __half As[2][128][40];
    __shared__ __half Bs[2][128][40];

    const int col0 = blockIdx.x * 128;
    const int m0   = blockIdx.y * 128;

    const int tid  = threadIdx.x;
    const int w    = tid >> 5;
    const int lane = tid & 31;
    const int g    = lane >> 2;
    const int tig  = lane & 3;
    const int wm   = (w & 1) * 64;
    const int wn   = (w >> 1) * 32;

    float acc[4][4][4];
    #pragma unroll
    for (int mt = 0; mt < 4; mt++)
        #pragma unroll
        for (int nt = 0; nt < 4; nt++)
            #pragma unroll
            for (int i = 0; i < 4; i++) acc[mt][nt][i] = 0.f;

    uint4 aS[2], bS[2];
    const uint4 z4 = make_uint4(0, 0, 0, 0);

    // stage one 128x32 K-tile of each array: 2 x uint4 per thread per array
    auto loadT = [&](int t) {
        const int k0 = t * BK;
        #pragma unroll
        for (int j = 0; j < 2; j++) {
            int id = tid + j * 256;           // 0..511
            int r  = id >> 2;                 // 0..127
            int c8 = (id & 3) * 8;            // 0,8,16,24 halves
            int gr = m0 + r;
            aS[j] = (gr < NNODES) ? *(const uint4*)(A + (size_t)gr * KPAD + k0 + c8) : z4;
            int gn = col0 + r;
            bS[j] = (gn < NTOT) ? *(const uint4*)(Bt + (size_t)gn * KPAD + k0 + c8) : z4;
        }
    };
    auto storeT = [&](int buf) {
        #pragma unroll
        for (int j = 0; j < 2; j++) {
            int id = tid + j * 256;
            int r  = id >> 2;
            int c8 = (id & 3) * 8;
            *(uint4*)&As[buf][r][c8] = aS[j];
            *(uint4*)&Bs[buf][r][c8] = bS[j];
        }
    };

    loadT(0);
    storeT(0);
    __syncthreads();

    for (int t = 0; t < KT; t++) {
        const int buf = t & 1;
        if (t + 1 < KT) loadT(t + 1);

        // B fragments: one ldmatrix.x4 per nt covers the whole BK=32
        uint32_t bq[4][4];
        #pragma unroll
        for (int nt = 0; nt < 4; nt++)
            ldm_x4(bq[nt][0], bq[nt][1], bq[nt][2], bq[nt][3],
                   &Bs[buf][wn + nt * 8 + (lane & 7)][(lane >> 3) << 3]);

        #pragma unroll
        for (int ks = 0; ks < 2; ks++) {
            const int k = ks * 16;
            uint32_t aq[4][4];
            #pragma unroll
            for (int mt = 0; mt < 4; mt++)
                ldm_x4(aq[mt][0], aq[mt][1], aq[mt][2], aq[mt][3],
                       &As[buf][wm + mt * 16 + (lane & 15)][k + ((lane >> 4) << 3)]);
            #pragma unroll
            for (int mt = 0; mt < 4; mt++)
                #pragma unroll
                for (int nt = 0; nt < 4; nt++)
                    mma_f16(acc[mt][nt][0], acc[mt][nt][1],
                            acc[mt][nt][2], acc[mt][nt][3],
                            aq[mt][0], aq[mt][1], aq[mt][2], aq[mt][3],
                            bq[nt][ks * 2], bq[nt][ks * 2 + 1]);
        }

        if (t + 1 < KT) storeT(buf ^ 1);
        __syncthreads();
    }

    #pragma unroll
    for (int mt = 0; mt < 4; mt++) {
        int gr0 = m0 + wm + mt * 16 + g;
        #pragma unroll
        for (int nt = 0; nt < 4; nt++) {
            int gc = col0 + wn + nt * 8 + tig * 2;
            if (gc + 1 >= NTOT) continue;
            if (gr0 < NNODES)
                *(__half2*)(C + (size_t)gr0 * NTOT + gc) =
                    __floats2half2_rn(acc[mt][nt][0], acc[mt][nt][1]);
            if (gr0 + 8 < NNODES)
                *(__half2*)(C + (size_t)(gr0 + 8) * NTOT + gc) =
                    __floats2half2_rn(acc[mt][nt][2], acc[mt][nt][3]);
        }
    }
}

// ================= CSR construction ==========================================
__global__ void zero_cnt_kernel() {
    int i = blockIdx.x * blockDim.x + threadIdx.x;
    if (i < BTOT) g_cnt[i] = 0;
}

__global__ void hist_kernel(const int* __restrict__ rows, int E) {
    const int d = blockIdx.y;
    int e = blockIdx.x * blockDim.x + threadIdx.x;
    if (e >= E) return;
    atomicAdd(&g_cnt[d * NNODES + rows[(size_t)d * E + e]], 1);
}

__global__ void scan1_kernel() {
    __shared__ int sh[1024];
    int i = blockIdx.x * 1024 + threadIdx.x;
    int v = (i < BTOT) ? g_cnt[i] : 0;
    sh[threadIdx.x] = v;
    __syncthreads();
    #pragma unroll
    for (int off = 1; off < 1024; off <<= 1) {
        int t = (threadIdx.x >= off) ? sh[threadIdx.x - off] : 0;
        __syncthreads();
        sh[threadIdx.x] += t;
        __syncthreads();
    }
    if (i < BTOT) g_rowptr[i] = sh[threadIdx.x] - v;
    if (threadIdx.x == 1023) g_bsum[blockIdx.x] = sh[1023];
}

__global__ void scan2_kernel() {
    __shared__ int sh[1024];
    int v = (threadIdx.x < SCAN_BLKS) ? g_bsum[threadIdx.x] : 0;
    sh[threadIdx.x] = v;
    __syncthreads();
    #pragma unroll
    for (int off = 1; off < 1024; off <<= 1) {
        int t = (threadIdx.x >= off) ? sh[threadIdx.x - off] : 0;
        __syncthreads();
        sh[threadIdx.x] += t;
        __syncthreads();
    }
    if (threadIdx.x < SCAN_BLKS) g_bsum[threadIdx.x] = sh[threadIdx.x] - v;
}

__global__ void scan3_kernel(int total) {
    int i = blockIdx.x * 1024 + threadIdx.x;
    if (i < BTOT) {
        g_rowptr[i] += g_bsum[blockIdx.x];
        g_cnt[i] = 0;
    }
    if (i == 0) g_rowptr[BTOT] = total;
}

__global__ void scatter_kernel(const int* __restrict__ rows,
                               const int* __restrict__ cols,
                               const float* __restrict__ vals, int E) {
    const int d = blockIdx.y;
    int e = blockIdx.x * blockDim.x + threadIdx.x;
    if (e >= E) return;
    size_t eo = (size_t)d * E + e;
    int bin = d * NNODES + rows[eo];
    int pos = g_rowptr[bin] + atomicAdd(&g_cnt[bin], 1);
    g_ecv[pos] = make_int2(cols[eo], __float_as_int(vals[eo]));
}

// ================= CSR SpMM layer 1 (fp16 gather, fp32 acc, -> fp16) =========
__global__ void __launch_bounds__(256)
spmm1_csr_kernel(const __half* __restrict__ sup1, const float* __restrict__ b1,
                 __half* __restrict__ h1h) {
    const int d    = blockIdx.y;
    const int wid  = threadIdx.x >> 5;
    const int lane = threadIdx.x & 31;
    const int row  = blockIdx.x * 8 + wid;
    if (row >= NNODES) return;

    const int bin = d * NNODES + row;
    int j         = g_rowptr[bin];
    const int end = g_rowptr[bin + 1];
    const int off = d * NHID + lane * 2;

    float2 acc = make_float2(0.f, 0.f);
    for (; j + 1 < end; j += 2) {
        int2 cv0 = g_ecv[j];
        int2 cv1 = g_ecv[j + 1];
        float v0 = __int_as_float(cv0.y);
        float v1 = __int_as_float(cv1.y);
        float2 s0 = __half22float2(*(const __half2*)(sup1 + (size_t)cv0.x * HCAT + off));
        float2 s1 = __half22float2(*(const __half2*)(sup1 + (size_t)cv1.x * HCAT + off));
        acc.x += v0 * s0.x + v1 * s1.x;
        acc.y += v0 * s0.y + v1 * s1.y;
    }
    if (j < end) {
        int2 cv = g_ecv[j];
        float v = __int_as_float(cv.y);
        float2 s = __half22float2(*(const __half2*)(sup1 + (size_t)cv.x * HCAT + off));
        acc.x += v * s.x;
        acc.y += v * s.y;
    }

    float2 b = *(const float2*)(b1 + off);
    acc.x = fmaxf(acc.x + b.x, 0.f);
    acc.y = fmaxf(acc.y + b.y, 0.f);
    *(__half2*)(h1h + (size_t)row * HCAT + off) = __floats2half2_rn(acc.x, acc.y);
}

// ================= fused CSR SpMM layer 2 + bias + relu + max-pool ===========
// One block per row. Warp w handles branches d = w, w+8, ... keeps a running
// max; SMEM reduce across the 8 warps; single write of out[row][0..49].
__global__ void __launch_bounds__(256)
spmm2_fused_kernel(const __half* __restrict__ sup2, const float* __restrict__ b2,
                   float* __restrict__ out) {
    __shared__ float sm[8][52];
    const int row  = blockIdx.x;
    const int wid  = threadIdx.x >> 5;
    const int lane = threadIdx.x & 31;
    const bool act = lane < 25;            // 25 lanes x float2 = 50 classes

    float2 wmax = make_float2(-1e30f, -1e30f);

    for (int d = wid; d < DIMB; d += 8) {
        const int bin = d * NNODES + row;
        int j         = g_rowptr[bin];
        const int end = g_rowptr[bin + 1];
        const int off = d * NC2 + lane * 2;

        float2 acc = make_float2(0.f, 0.f);
        for (; j + 1 < end; j += 2) {
            int2 cv0 = g_ecv[j];
            int2 cv1 = g_ecv[j + 1];
            if (act) {
                float v0 = __int_as_float(cv0.y);
                float v1 = __int_as_float(cv1.y);
                float2 s0 = __half22float2(*(const __half2*)(sup2 + (size_t)cv0.x * NW2 + off));
                float2 s1 = __half22float2(*(const __half2*)(sup2 + (size_t)cv1.x * NW2 + off));
                acc.x += v0 * s0.x + v1 * s1.x;
                acc.y += v0 * s0.y + v1 * s1.y;
            }
        }
        if (j < end && act) {
            int2 cv = g_ecv[j];
            float v = __int_as_float(cv.y);
            float2 s = __half22float2(*(const __half2*)(sup2 + (size_t)cv.x * NW2 + off));
            acc.x += v * s.x;
            acc.y += v * s.y;
        }
        if (act) {
            float2 b = *(const float2*)(b2 + d * NCLASS + lane * 2);
            wmax.x = fmaxf(wmax.x, acc.x + b.x);
            wmax.y = fmaxf(wmax.y, acc.y + b.y);
        }
    }

    if (act) {
        sm[wid][lane * 2]     = wmax.x;
        sm[wid][lane * 2 + 1] = wmax.y;
    }
    __syncthreads();

    int c = threadIdx.x;
    if (c < NCLASS) {
        float m = 0.f;                      // relu folds into the max
        #pragma unroll
        for (int ww = 0; ww < 8; ww++) m = fmaxf(m, sm[ww][c]);
        out[(size_t)row * NCLASS + c] = m;
    }
}

// ================= launch ====================================================
extern "C" void kernel_launch(void* const* d_in, const int* in_sizes, int n_in,
                              void* d_out, int out_size) {
    const float* x        = (const float*)d_in[0];
    const int*   adj_rows = (const int*)d_in[1];
    const int*   adj_cols = (const int*)d_in[2];
    const float* adj_vals = (const float*)d_in[3];
    const float* W1       = (const float*)d_in[4];
    const float* b1       = (const float*)d_in[5];
    const float* W2       = (const float*)d_in[6];
    const float* b2       = (const float*)d_in[7];
    float*       out      = (float*)d_out;

    const int E = in_sizes[1] / DIMB;

    __half *p_xh, *p_w1h, *p_w2h, *p_h1h, *p_sup1, *p_sup2;
    cudaGetSymbolAddress((void**)&p_xh,   g_xh);
    cudaGetSymbolAddress((void**)&p_w1h,  g_w1h);
    cudaGetSymbolAddress((void**)&p_w2h,  g_w2h);
    cudaGetSymbolAddress((void**)&p_sup1, g_sup1);
    cudaGetSymbolAddress((void**)&p_h1h,  g_h1h);
    cudaGetSymbolAddress((void**)&p_sup2, g_sup2);

    const dim3 egrid((E + 255) / 256, DIMB);
    const int mTiles = (NNODES + 127) / 128;

    // --- prep + GEMM1 first (keeps h_mma_kernel at ncu's captured index) -----
    cvt_x_kernel<<<(NNODES * KPAD1 / 4 + 255) / 256, 256>>>(x, p_xh);
    repack1_kernel<<<(HCAT * KPAD1 + 255) / 256, 256>>>(W1, p_w1h);
    repack2_kernel<<<(NW2 * HCAT + 255) / 256, 256>>>(W2, p_w2h);
    h_mma_kernel<KPAD1, HCAT>
        <<<dim3((HCAT + 127) / 128, mTiles), 256>>>(p_xh, p_w1h, p_sup1);

    // --- CSR build -----------------------------------------------------------
    zero_cnt_kernel<<<(BTOT + 255) / 256, 256>>>();
    hist_kernel<<<egrid, 256>>>(adj_rows, E);
    scan1_kernel<<<SCAN_BLKS, 1024>>>();
    scan2_kernel<<<1, 1024>>>();
    scan3_kernel<<<SCAN_BLKS, 1024>>>(DIMB * E);
    scatter_kernel<<<egrid, 256>>>(adj_rows, adj_cols, adj_vals, E);

    // --- layer 1 spmm (fused bias/relu -> fp16) ------------------------------
    spmm1_csr_kernel<<<dim3(NNODES / 8, DIMB), 256>>>(p_sup1, b1, p_h1h);

    // --- layer 2: fp16 GEMM + fused spmm/bias/relu/max -----------------------
    h_mma_kernel<HCAT, NW2>
        <<<dim3((NW2 + 127) / 128, mTiles), 256>>>(p_h1h, p_w2h, p_sup2);
    spmm2_fused_kernel<<<NNODES, 256>>>(p_sup2, b2, out);
}

// round 11
// speedup vs baseline: 1.0457x; 1.0457x over previous
#include <cuda_runtime.h>
#include <cuda_fp16.h>
#include <cstdint>
#include <cstdio>

#define DIMB   25
#define NNODES 20000
#define NFEAT  300
#define KPAD1  320            // NFEAT padded to multiple of 64
#define NHID   64
#define NCLASS 50
#define NC2    52             // NCLASS padded to 52
#define HCAT   (DIMB * NHID)  // 1600 (K of layer-2 GEMM, %64==0)
#define NW2    (DIMB * NC2)   // 1300
#define EDGES  320000
#define BTOT   (DIMB * NNODES)
#define SCAN_BLKS ((BTOT + 1023) / 1024)

// ---------------- scratch (static device memory; no allocs allowed) ----------
__device__ __half g_xh  [(size_t)NNODES * KPAD1];
__device__ __half g_w1h [(size_t)HCAT * KPAD1];
__device__ __half g_w2h [(size_t)NW2 * HCAT];
__device__ __half g_sup1[(size_t)NNODES * HCAT];
__device__ __half g_h1h [(size_t)NNODES * HCAT];
__device__ __half g_sup2[(size_t)NNODES * NW2];
// CSR build
__device__ int   g_cnt   [BTOT];
__device__ int   g_rowptr[BTOT + 1];
__device__ int   g_bsum  [1024];
__device__ int2  g_ecv   [(size_t)DIMB * EDGES];

// ---------------- helpers ----------------------------------------------------
__device__ __forceinline__ void mma_f16(float& c0, float& c1, float& c2, float& c3,
                                        uint32_t a0, uint32_t a1, uint32_t a2, uint32_t a3,
                                        uint32_t b0, uint32_t b1) {
    asm volatile("mma.sync.aligned.m16n8k16.row.col.f32.f16.f16.f32 "
                 "{%0,%1,%2,%3}, {%4,%5,%6,%7}, {%8,%9}, {%0,%1,%2,%3};"
                 : "+f"(c0), "+f"(c1), "+f"(c2), "+f"(c3)
                 : "r"(a0), "r"(a1), "r"(a2), "r"(a3), "r"(b0), "r"(b1));
}

// ================= prep ======================================================
__global__ void cvt_x_kernel(const float* __restrict__ x, __half* __restrict__ xh) {
    size_t i = (size_t)blockIdx.x * blockDim.x + threadIdx.x;
    if (i >= (size_t)NNODES * KPAD1 / 4) return;
    int n   = (int)(i / (KPAD1 / 4));
    int col = ((int)(i % (KPAD1 / 4))) * 4;
    __half2 lo = __floats2half2_rn(0.f, 0.f), hi = lo;
    if (col < NFEAT) {
        float4 v = *(const float4*)(x + (size_t)n * NFEAT + col);
        lo = __floats2half2_rn(v.x, v.y);
        hi = __floats2half2_rn(v.z, v.w);
    }
    *(uint2*)(xh + i * 4) = make_uint2(*(uint32_t*)&lo, *(uint32_t*)&hi);
}

__global__ void repack1_kernel(const float* __restrict__ W1, __half* __restrict__ B1) {
    int i = blockIdx.x * blockDim.x + threadIdx.x;
    if (i >= HCAT * KPAD1) return;
    int n = i / KPAD1, k = i - n * KPAD1;
    int d = n >> 6, h = n & 63;
    B1[i] = (k < NFEAT) ? __float2half_rn(W1[((size_t)d * NFEAT + k) * NHID + h])
                        : __float2half_rn(0.f);
}

__global__ void repack2_kernel(const float* __restrict__ W2, __half* __restrict__ B2) {
    int i = blockIdx.x * blockDim.x + threadIdx.x;
    if (i >= NW2 * HCAT) return;
    int n = i / HCAT, k = i - n * HCAT;
    int d = n / NC2, c = n - d * NC2;
    B2[i] = (c < NCLASS) ? __float2half_rn(W2[((size_t)d * HCAT + k) * NCLASS + c])
                         : __float2half_rn(0.f);
}

// ================= fp16 tensor-core GEMM (R9 proven variant) =================
// C (NNODES x NTOT, fp16) = A (NNODES x KPAD) * Bt (NTOT x KPAD)^T.
// BM=BN=128, BK=64, 8 warps 2(m)x4(n), warp tile 64x32, m16n8k16.
// Single-buffered SMEM + register prefetch; stride-72 rows conflict-free.
template <int KPAD, int NTOT>
__global__ void __launch_bounds__(256, 2)
h_mma_kernel(const __half* __restrict__ A, const __half* __restrict__ Bt,
             __half* __restrict__ C) {
    constexpr int BK = 64;
    constexpr int KT = KPAD / BK;
    __shared__ __half As[128][72];
    __shared__ __half Bs[128][72];

    const int col0 = blockIdx.x * 128;
    const int m0   = blockIdx.y * 128;

    const int tid  = threadIdx.x;
    const int w    = tid >> 5;
    const int lane = tid & 31;
    const int g    = lane >> 2;
    const int tig  = lane & 3;
    const int wm   = (w & 1) * 64;
    const int wn   = (w >> 1) * 32;

    float acc[4][4][4];
    #pragma unroll
    for (int mt = 0; mt < 4; mt++)
        #pragma unroll
        for (int nt = 0; nt < 4; nt++)
            #pragma unroll
            for (int i = 0; i < 4; i++) acc[mt][nt][i] = 0.f;

    uint4 aS[4], bS[4];
    const uint4 z4 = make_uint4(0, 0, 0, 0);

    auto loadT = [&](int k0) {
        #pragma unroll
        for (int j = 0; j < 4; j++) {
            int id = tid + j * 256;
            int r  = id >> 3;
            int c8 = (id & 7) * 8;
            int gr = m0 + r;
            aS[j] = (gr < NNODES) ? *(const uint4*)(A + (size_t)gr * KPAD + k0 + c8) : z4;
            int gn = col0 + r;
            bS[j] = (gn < NTOT) ? *(const uint4*)(Bt + (size_t)gn * KPAD + k0 + c8) : z4;
        }
    };
    auto storeT = [&]() {
        #pragma unroll
        for (int j = 0; j < 4; j++) {
            int id = tid + j * 256;
            int r  = id >> 3;
            int c8 = (id & 7) * 8;
            *(uint4*)&As[r][c8] = aS[j];
            *(uint4*)&Bs[r][c8] = bS[j];
        }
    };

    loadT(0);

    for (int t = 0; t < KT; t++) {
        storeT();
        __syncthreads();
        if (t + 1 < KT) loadT((t + 1) * BK);

        #pragma unroll
        for (int ks = 0; ks < 4; ks++) {
            const int k = ks * 16;
            uint32_t a[4][4];
            #pragma unroll
            for (int mt = 0; mt < 4; mt++) {
                int m = wm + mt * 16;
                a[mt][0] = *(const uint32_t*)&As[m + g    ][k + 2 * tig    ];
                a[mt][1] = *(const uint32_t*)&As[m + g + 8][k + 2 * tig    ];
                a[mt][2] = *(const uint32_t*)&As[m + g    ][k + 2 * tig + 8];
                a[mt][3] = *(const uint32_t*)&As[m + g + 8][k + 2 * tig + 8];
            }
            uint32_t b[4][2];
            #pragma unroll
            for (int nt = 0; nt < 4; nt++) {
                int n = wn + nt * 8;
                b[nt][0] = *(const uint32_t*)&Bs[n + g][k + 2 * tig    ];
                b[nt][1] = *(const uint32_t*)&Bs[n + g][k + 2 * tig + 8];
            }
            #pragma unroll
            for (int mt = 0; mt < 4; mt++)
                #pragma unroll
                for (int nt = 0; nt < 4; nt++)
                    mma_f16(acc[mt][nt][0], acc[mt][nt][1],
                            acc[mt][nt][2], acc[mt][nt][3],
                            a[mt][0], a[mt][1], a[mt][2], a[mt][3],
                            b[nt][0], b[nt][1]);
        }
        __syncthreads();
    }

    #pragma unroll
    for (int mt = 0; mt < 4; mt++) {
        int gr0 = m0 + wm + mt * 16 + g;
        #pragma unroll
        for (int nt = 0; nt < 4; nt++) {
            int gc = col0 + wn + nt * 8 + tig * 2;
            if (gc + 1 >= NTOT) continue;
            if (gr0 < NNODES)
                *(__half2*)(C + (size_t)gr0 * NTOT + gc) =
                    __floats2half2_rn(acc[mt][nt][0], acc[mt][nt][1]);
            if (gr0 + 8 < NNODES)
                *(__half2*)(C + (size_t)(gr0 + 8) * NTOT + gc) =
                    __floats2half2_rn(acc[mt][nt][2], acc[mt][nt][3]);
        }
    }
}

// ================= CSR construction ==========================================
__global__ void zero_cnt_kernel() {
    int i = blockIdx.x * blockDim.x + threadIdx.x;
    if (i < BTOT) g_cnt[i] = 0;
}

__global__ void hist_kernel(const int* __restrict__ rows, int E) {
    const int d = blockIdx.y;
    int e = blockIdx.x * blockDim.x + threadIdx.x;
    if (e >= E) return;
    atomicAdd(&g_cnt[d * NNODES + rows[(size_t)d * E + e]], 1);
}

__global__ void scan1_kernel() {
    __shared__ int sh[1024];
    int i = blockIdx.x * 1024 + threadIdx.x;
    int v = (i < BTOT) ? g_cnt[i] : 0;
    sh[threadIdx.x] = v;
    __syncthreads();
    #pragma unroll
    for (int off = 1; off < 1024; off <<= 1) {
        int t = (threadIdx.x >= off) ? sh[threadIdx.x - off] : 0;
        __syncthreads();
        sh[threadIdx.x] += t;
        __syncthreads();
    }
    if (i < BTOT) g_rowptr[i] = sh[threadIdx.x] - v;
    if (threadIdx.x == 1023) g_bsum[blockIdx.x] = sh[1023];
}

__global__ void scan2_kernel() {
    __shared__ int sh[1024];
    int v = (threadIdx.x < SCAN_BLKS) ? g_bsum[threadIdx.x] : 0;
    sh[threadIdx.x] = v;
    __syncthreads();
    #pragma unroll
    for (int off = 1; off < 1024; off <<= 1) {
        int t = (threadIdx.x >= off) ? sh[threadIdx.x - off] : 0;
        __syncthreads();
        sh[threadIdx.x] += t;
        __syncthreads();
    }
    if (threadIdx.x < SCAN_BLKS) g_bsum[threadIdx.x] = sh[threadIdx.x] - v;
}

__global__ void scan3_kernel(int total) {
    int i = blockIdx.x * 1024 + threadIdx.x;
    if (i < BTOT) {
        g_rowptr[i] += g_bsum[blockIdx.x];
        g_cnt[i] = 0;
    }
    if (i == 0) g_rowptr[BTOT] = total;
}

__global__ void scatter_kernel(const int* __restrict__ rows,
                               const int* __restrict__ cols,
                               const float* __restrict__ vals, int E) {
    const int d = blockIdx.y;
    int e = blockIdx.x * blockDim.x + threadIdx.x;
    if (e >= E) return;
    size_t eo = (size_t)d * E + e;
    int bin = d * NNODES + rows[eo];
    int pos = g_rowptr[bin] + atomicAdd(&g_cnt[bin], 1);
    g_ecv[pos] = make_int2(cols[eo], __float_as_int(vals[eo]));
}

// ================= CSR SpMM layer 1 (fp16 gather, fp32 acc, -> fp16) =========
__global__ void __launch_bounds__(256)
spmm1_csr_kernel(const __half* __restrict__ sup1, const float* __restrict__ b1,
                 __half* __restrict__ h1h) {
    const int d    = blockIdx.y;
    const int wid  = threadIdx.x >> 5;
    const int lane = threadIdx.x & 31;
    const int row  = blockIdx.x * 8 + wid;
    if (row >= NNODES) return;

    const int bin = d * NNODES + row;
    int j         = g_rowptr[bin];
    const int end = g_rowptr[bin + 1];
    const int off = d * NHID + lane * 2;

    float2 acc = make_float2(0.f, 0.f);
    for (; j + 1 < end; j += 2) {
        int2 cv0 = g_ecv[j];
        int2 cv1 = g_ecv[j + 1];
        float v0 = __int_as_float(cv0.y);
        float v1 = __int_as_float(cv1.y);
        float2 s0 = __half22float2(*(const __half2*)(sup1 + (size_t)cv0.x * HCAT + off));
        float2 s1 = __half22float2(*(const __half2*)(sup1 + (size_t)cv1.x * HCAT + off));
        acc.x += v0 * s0.x + v1 * s1.x;
        acc.y += v0 * s0.y + v1 * s1.y;
    }
    if (j < end) {
        int2 cv = g_ecv[j];
        float v = __int_as_float(cv.y);
        float2 s = __half22float2(*(const __half2*)(sup1 + (size_t)cv.x * HCAT + off));
        acc.x += v * s.x;
        acc.y += v * s.y;
    }

    float2 b = *(const float2*)(b1 + off);
    acc.x = fmaxf(acc.x + b.x, 0.f);
    acc.y = fmaxf(acc.y + b.y, 0.f);
    *(__half2*)(h1h + (size_t)row * HCAT + off) = __floats2half2_rn(acc.x, acc.y);
}

// ================= fused CSR SpMM layer 2 + bias + relu + max-pool ===========
__global__ void __launch_bounds__(256)
spmm2_fused_kernel(const __half* __restrict__ sup2, const float* __restrict__ b2,
                   float* __restrict__ out) {
    __shared__ float sm[8][52];
    const int row  = blockIdx.x;
    const int wid  = threadIdx.x >> 5;
    const int lane = threadIdx.x & 31;
    const bool act = lane < 25;            // 25 lanes x float2 = 50 classes

    float2 wmax = make_float2(-1e30f, -1e30f);

    for (int d = wid; d < DIMB; d += 8) {
        const int bin = d * NNODES + row;
        int j         = g_rowptr[bin];
        const int end = g_rowptr[bin + 1];
        const int off = d * NC2 + lane * 2;

        float2 acc = make_float2(0.f, 0.f);
        for (; j + 1 < end; j += 2) {
            int2 cv0 = g_ecv[j];
            int2 cv1 = g_ecv[j + 1];
            if (act) {
                float v0 = __int_as_float(cv0.y);
                float v1 = __int_as_float(cv1.y);
                float2 s0 = __half22float2(*(const __half2*)(sup2 + (size_t)cv0.x * NW2 + off));
                float2 s1 = __half22float2(*(const __half2*)(sup2 + (size_t)cv1.x * NW2 + off));
                acc.x += v0 * s0.x + v1 * s1.x;
                acc.y += v0 * s0.y + v1 * s1.y;
            }
        }
        if (j < end && act) {
            int2 cv = g_ecv[j];
            float v = __int_as_float(cv.y);
            float2 s = __half22float2(*(const __half2*)(sup2 + (size_t)cv.x * NW2 + off));
            acc.x += v * s.x;
            acc.y += v * s.y;
        }
        if (act) {
            float2 b = *(const float2*)(b2 + d * NCLASS + lane * 2);
            wmax.x = fmaxf(wmax.x, acc.x + b.x);
            wmax.y = fmaxf(wmax.y, acc.y + b.y);
        }
    }

    if (act) {
        sm[wid][lane * 2]     = wmax.x;
        sm[wid][lane * 2 + 1] = wmax.y;
    }
    __syncthreads();

    int c = threadIdx.x;
    if (c < NCLASS) {
        float m = 0.f;                      // relu folds into the max
        #pragma unroll
        for (int ww = 0; ww < 8; ww++) m = fmaxf(m, sm[ww][c]);
        out[(size_t)row * NCLASS + c] = m;
    }
}

// ================= launch ====================================================
extern "C" void kernel_launch(void* const* d_in, const int* in_sizes, int n_in,
                              void* d_out, int out_size) {
    const float* x        = (const float*)d_in[0];
    const int*   adj_rows = (const int*)d_in[1];
    const int*   adj_cols = (const int*)d_in[2];
    const float* adj_vals = (const float*)d_in[3];
    const float* W1       = (const float*)d_in[4];
    const float* b1       = (const float*)d_in[5];
    const float* W2       = (const float*)d_in[6];
    const float* b2       = (const float*)d_in[7];
    float*       out      = (float*)d_out;

    const int E = in_sizes[1] / DIMB;

    __half *p_xh, *p_w1h, *p_w2h, *p_h1h, *p_sup1, *p_sup2;
    cudaGetSymbolAddress((void**)&p_xh,   g_xh);
    cudaGetSymbolAddress((void**)&p_w1h,  g_w1h);
    cudaGetSymbolAddress((void**)&p_w2h,  g_w2h);
    cudaGetSymbolAddress((void**)&p_sup1, g_sup1);
    cudaGetSymbolAddress((void**)&p_h1h,  g_h1h);
    cudaGetSymbolAddress((void**)&p_sup2, g_sup2);

    const dim3 egrid((E + 255) / 256, DIMB);
    const int mTiles = (NNODES + 127) / 128;

    // --- prep + GEMM1 first (keeps h_mma_kernel at ncu's captured index) -----
    cvt_x_kernel<<<(NNODES * KPAD1 / 4 + 255) / 256, 256>>>(x, p_xh);
    repack1_kernel<<<(HCAT * KPAD1 + 255) / 256, 256>>>(W1, p_w1h);
    repack2_kernel<<<(NW2 * HCAT + 255) / 256, 256>>>(W2, p_w2h);
    h_mma_kernel<KPAD1, HCAT>
        <<<dim3((HCAT + 127) / 128, mTiles), 256>>>(p_xh, p_w1h, p_sup1);

    // --- CSR build -----------------------------------------------------------
    zero_cnt_kernel<<<(BTOT + 255) / 256, 256>>>();
    hist_kernel<<<egrid, 256>>>(adj_rows, E);
    scan1_kernel<<<SCAN_BLKS, 1024>>>();
    scan2_kernel<<<1, 1024>>>();
    scan3_kernel<<<SCAN_BLKS, 1024>>>(DIMB * E);
    scatter_kernel<<<egrid, 256>>>(adj_rows, adj_cols, adj_vals, E);

    // --- layer 1 spmm (fused bias/relu -> fp16) ------------------------------
    spmm1_csr_kernel<<<dim3(NNODES / 8, DIMB), 256>>>(p_sup1, b1, p_h1h);

    // --- layer 2: fp16 GEMM + fused spmm/bias/relu/max -----------------------
    h_mma_kernel<HCAT, NW2>
        <<<dim3((NW2 + 127) / 128, mTiles), 256>>>(p_h1h, p_w2h, p_sup2);
    spmm2_fused_kernel<<<NNODES, 256>>>(p_sup2, b2, out);
}

// round 12
// speedup vs baseline: 1.0570x; 1.0108x over previous
#include <cuda_runtime.h>
#include <cuda_fp16.h>
#include <cstdint>
#include <cstdio>

#define DIMB   25
#define NNODES 20000
#define NFEAT  300
#define KPAD1  320            // NFEAT padded to multiple of 64
#define NHID   64
#define NCLASS 50
#define NC2    52             // NCLASS padded to 52
#define HCAT   (DIMB * NHID)  // 1600 (K of layer-2 GEMM, %64==0)
#define NW2    (DIMB * NC2)   // 1300
#define EDGES  320000
#define BTOT   (DIMB * NNODES)
#define SCAN_BLKS ((BTOT + 1023) / 1024)

// ---------------- scratch (static device memory; no allocs allowed) ----------
__device__ __half g_xh  [(size_t)NNODES * KPAD1];
__device__ __half g_w1h [(size_t)HCAT * KPAD1];
__device__ __half g_w2h [(size_t)NW2 * HCAT];
__device__ __half g_sup1[(size_t)NNODES * HCAT];
__device__ __half g_h1h [(size_t)NNODES * HCAT];
__device__ __half g_sup2[(size_t)NNODES * NW2];
// CSR build
__device__ int   g_cnt   [BTOT];
__device__ int   g_rowptr[BTOT + 1];
__device__ int   g_bsum  [1024];
__device__ int2  g_ecv   [(size_t)DIMB * EDGES];

// ---------------- helpers ----------------------------------------------------
__device__ __forceinline__ void mma_f16(float& c0, float& c1, float& c2, float& c3,
                                        uint32_t a0, uint32_t a1, uint32_t a2, uint32_t a3,
                                        uint32_t b0, uint32_t b1) {
    asm volatile("mma.sync.aligned.m16n8k16.row.col.f32.f16.f16.f32 "
                 "{%0,%1,%2,%3}, {%4,%5,%6,%7}, {%8,%9}, {%0,%1,%2,%3};"
                 : "+f"(c0), "+f"(c1), "+f"(c2), "+f"(c3)
                 : "r"(a0), "r"(a1), "r"(a2), "r"(a3), "r"(b0), "r"(b1));
}

__device__ __forceinline__ void ldm_x4(uint32_t& r0, uint32_t& r1,
                                       uint32_t& r2, uint32_t& r3, const void* p) {
    uint32_t addr = (uint32_t)__cvta_generic_to_shared(p);
    asm volatile("ldmatrix.sync.aligned.m8n8.x4.shared.b16 {%0,%1,%2,%3}, [%4];"
                 : "=r"(r0), "=r"(r1), "=r"(r2), "=r"(r3) : "r"(addr));
}

// ================= prep ======================================================
__global__ void cvt_x_kernel(const float* __restrict__ x, __half* __restrict__ xh) {
    size_t i = (size_t)blockIdx.x * blockDim.x + threadIdx.x;
    if (i >= (size_t)NNODES * KPAD1 / 4) return;
    int n   = (int)(i / (KPAD1 / 4));
    int col = ((int)(i % (KPAD1 / 4))) * 4;
    __half2 lo = __floats2half2_rn(0.f, 0.f), hi = lo;
    if (col < NFEAT) {
        float4 v = *(const float4*)(x + (size_t)n * NFEAT + col);
        lo = __floats2half2_rn(v.x, v.y);
        hi = __floats2half2_rn(v.z, v.w);
    }
    *(uint2*)(xh + i * 4) = make_uint2(*(uint32_t*)&lo, *(uint32_t*)&hi);
}

__global__ void repack1_kernel(const float* __restrict__ W1, __half* __restrict__ B1) {
    int i = blockIdx.x * blockDim.x + threadIdx.x;
    if (i >= HCAT * KPAD1) return;
    int n = i / KPAD1, k = i - n * KPAD1;
    int d = n >> 6, h = n & 63;
    B1[i] = (k < NFEAT) ? __float2half_rn(W1[((size_t)d * NFEAT + k) * NHID + h])
                        : __float2half_rn(0.f);
}

__global__ void repack2_kernel(const float* __restrict__ W2, __half* __restrict__ B2) {
    int i = blockIdx.x * blockDim.x + threadIdx.x;
    if (i >= NW2 * HCAT) return;
    int n = i / HCAT, k = i - n * HCAT;
    int d = n / NC2, c = n - d * NC2;
    B2[i] = (c < NCLASS) ? __float2half_rn(W2[((size_t)d * HCAT + k) * NCLASS + c])
                         : __float2half_rn(0.f);
}

// ================= fp16 tensor-core GEMM =====================================
// C (NNODES x NTOT, fp16) = A (NNODES x KPAD) * Bt (NTOT x KPAD)^T.
// BM=BN=128, BK=64, 8 warps 2(m)x4(n), warp tile 64x32, m16n8k16.
// Single-buffered SMEM + register prefetch (proven R9 pipeline) with
// ldmatrix.x4 fragment loads (conflict-free on stride-72 rows).
template <int KPAD, int NTOT>
__global__ void __launch_bounds__(256, 2)
h_mma_kernel(const __half* __restrict__ A, const __half* __restrict__ Bt,
             __half* __restrict__ C) {
    constexpr int BK = 64;
    constexpr int KT = KPAD / BK;
    __shared__ __half As[128][72];
    __shared__ __half Bs[128][72];

    const int col0 = blockIdx.x * 128;
    const int m0   = blockIdx.y * 128;

    const int tid  = threadIdx.x;
    const int w    = tid >> 5;
    const int lane = tid & 31;
    const int g    = lane >> 2;
    const int tig  = lane & 3;
    const int wm   = (w & 1) * 64;
    const int wn   = (w >> 1) * 32;

    float acc[4][4][4];
    #pragma unroll
    for (int mt = 0; mt < 4; mt++)
        #pragma unroll
        for (int nt = 0; nt < 4; nt++)
            #pragma unroll
            for (int i = 0; i < 4; i++) acc[mt][nt][i] = 0.f;

    uint4 aS[4], bS[4];
    const uint4 z4 = make_uint4(0, 0, 0, 0);

    auto loadT = [&](int k0) {
        #pragma unroll
        for (int j = 0; j < 4; j++) {
            int id = tid + j * 256;
            int r  = id >> 3;
            int c8 = (id & 7) * 8;
            int gr = m0 + r;
            aS[j] = (gr < NNODES) ? *(const uint4*)(A + (size_t)gr * KPAD + k0 + c8) : z4;
            int gn = col0 + r;
            bS[j] = (gn < NTOT) ? *(const uint4*)(Bt + (size_t)gn * KPAD + k0 + c8) : z4;
        }
    };
    auto storeT = [&]() {
        #pragma unroll
        for (int j = 0; j < 4; j++) {
            int id = tid + j * 256;
            int r  = id >> 3;
            int c8 = (id & 7) * 8;
            *(uint4*)&As[r][c8] = aS[j];
            *(uint4*)&Bs[r][c8] = bS[j];
        }
    };

    loadT(0);

    for (int t = 0; t < KT; t++) {
        storeT();
        __syncthreads();
        if (t + 1 < KT) loadT((t + 1) * BK);

        #pragma unroll
        for (int half = 0; half < 2; half++) {
            const int kh = half * 32;
            // B fragments: one ldmatrix.x4 per nt covers kh..kh+31 (2 ks)
            uint32_t bq[4][4];
            #pragma unroll
            for (int nt = 0; nt < 4; nt++)
                ldm_x4(bq[nt][0], bq[nt][1], bq[nt][2], bq[nt][3],
                       &Bs[wn + nt * 8 + (lane & 7)][kh + ((lane >> 3) << 3)]);

            #pragma unroll
            for (int ks = 0; ks < 2; ks++) {
                const int k = kh + ks * 16;
                uint32_t aq[4][4];
                #pragma unroll
                for (int mt = 0; mt < 4; mt++)
                    ldm_x4(aq[mt][0], aq[mt][1], aq[mt][2], aq[mt][3],
                           &As[wm + mt * 16 + (lane & 15)][k + ((lane >> 4) << 3)]);
                #pragma unroll
                for (int mt = 0; mt < 4; mt++)
                    #pragma unroll
                    for (int nt = 0; nt < 4; nt++)
                        mma_f16(acc[mt][nt][0], acc[mt][nt][1],
                                acc[mt][nt][2], acc[mt][nt][3],
                                aq[mt][0], aq[mt][1], aq[mt][2], aq[mt][3],
                                bq[nt][ks * 2], bq[nt][ks * 2 + 1]);
            }
        }
        __syncthreads();
    }

    #pragma unroll
    for (int mt = 0; mt < 4; mt++) {
        int gr0 = m0 + wm + mt * 16 + g;
        #pragma unroll
        for (int nt = 0; nt < 4; nt++) {
            int gc = col0 + wn + nt * 8 + tig * 2;
            if (gc + 1 >= NTOT) continue;
            if (gr0 < NNODES)
                *(__half2*)(C + (size_t)gr0 * NTOT + gc) =
                    __floats2half2_rn(acc[mt][nt][0], acc[mt][nt][1]);
            if (gr0 + 8 < NNODES)
                *(__half2*)(C + (size_t)(gr0 + 8) * NTOT + gc) =
                    __floats2half2_rn(acc[mt][nt][2], acc[mt][nt][3]);
        }
    }
}

// ================= CSR construction ==========================================
__global__ void zero_cnt_kernel() {
    int i = blockIdx.x * blockDim.x + threadIdx.x;
    if (i < BTOT) g_cnt[i] = 0;
}

__global__ void hist_kernel(const int* __restrict__ rows, int E) {
    const int d = blockIdx.y;
    int e = blockIdx.x * blockDim.x + threadIdx.x;
    if (e >= E) return;
    atomicAdd(&g_cnt[d * NNODES + rows[(size_t)d * E + e]], 1);
}

__global__ void scan1_kernel() {
    __shared__ int sh[1024];
    int i = blockIdx.x * 1024 + threadIdx.x;
    int v = (i < BTOT) ? g_cnt[i] : 0;
    sh[threadIdx.x] = v;
    __syncthreads();
    #pragma unroll
    for (int off = 1; off < 1024; off <<= 1) {
        int t = (threadIdx.x >= off) ? sh[threadIdx.x - off] : 0;
        __syncthreads();
        sh[threadIdx.x] += t;
        __syncthreads();
    }
    if (i < BTOT) g_rowptr[i] = sh[threadIdx.x] - v;
    if (threadIdx.x == 1023) g_bsum[blockIdx.x] = sh[1023];
}

__global__ void scan2_kernel() {
    __shared__ int sh[1024];
    int v = (threadIdx.x < SCAN_BLKS) ? g_bsum[threadIdx.x] : 0;
    sh[threadIdx.x] = v;
    __syncthreads();
    #pragma unroll
    for (int off = 1; off < 1024; off <<= 1) {
        int t = (threadIdx.x >= off) ? sh[threadIdx.x - off] : 0;
        __syncthreads();
        sh[threadIdx.x] += t;
        __syncthreads();
    }
    if (threadIdx.x < SCAN_BLKS) g_bsum[threadIdx.x] = sh[threadIdx.x] - v;
}

__global__ void scan3_kernel(int total) {
    int i = blockIdx.x * 1024 + threadIdx.x;
    if (i < BTOT) {
        g_rowptr[i] += g_bsum[blockIdx.x];
        g_cnt[i] = 0;
    }
    if (i == 0) g_rowptr[BTOT] = total;
}

__global__ void scatter_kernel(const int* __restrict__ rows,
                               const int* __restrict__ cols,
                               const float* __restrict__ vals, int E) {
    const int d = blockIdx.y;
    int e = blockIdx.x * blockDim.x + threadIdx.x;
    if (e >= E) return;
    size_t eo = (size_t)d * E + e;
    int bin = d * NNODES + rows[eo];
    int pos = g_rowptr[bin] + atomicAdd(&g_cnt[bin], 1);
    g_ecv[pos] = make_int2(cols[eo], __float_as_int(vals[eo]));
}

// ================= CSR SpMM layer 1 (fp16 gather, fp32 acc, -> fp16) =========
__global__ void __launch_bounds__(256)
spmm1_csr_kernel(const __half* __restrict__ sup1, const float* __restrict__ b1,
                 __half* __restrict__ h1h) {
    const int d    = blockIdx.y;
    const int wid  = threadIdx.x >> 5;
    const int lane = threadIdx.x & 31;
    const int row  = blockIdx.x * 8 + wid;
    if (row >= NNODES) return;

    const int bin = d * NNODES + row;
    int j         = g_rowptr[bin];
    const int end = g_rowptr[bin + 1];
    const int off = d * NHID + lane * 2;

    float2 acc = make_float2(0.f, 0.f);
    for (; j + 1 < end; j += 2) {
        int2 cv0 = g_ecv[j];
        int2 cv1 = g_ecv[j + 1];
        float v0 = __int_as_float(cv0.y);
        float v1 = __int_as_float(cv1.y);
        float2 s0 = __half22float2(*(const __half2*)(sup1 + (size_t)cv0.x * HCAT + off));
        float2 s1 = __half22float2(*(const __half2*)(sup1 + (size_t)cv1.x * HCAT + off));
        acc.x += v0 * s0.x + v1 * s1.x;
        acc.y += v0 * s0.y + v1 * s1.y;
    }
    if (j < end) {
        int2 cv = g_ecv[j];
        float v = __int_as_float(cv.y);
        float2 s = __half22float2(*(const __half2*)(sup1 + (size_t)cv.x * HCAT + off));
        acc.x += v * s.x;
        acc.y += v * s.y;
    }

    float2 b = *(const float2*)(b1 + off);
    acc.x = fmaxf(acc.x + b.x, 0.f);
    acc.y = fmaxf(acc.y + b.y, 0.f);
    *(__half2*)(h1h + (size_t)row * HCAT + off) = __floats2half2_rn(acc.x, acc.y);
}

// ================= fused CSR SpMM layer 2 + bias + relu + max-pool ===========
__global__ void __launch_bounds__(256)
spmm2_fused_kernel(const __half* __restrict__ sup2, const float* __restrict__ b2,
                   float* __restrict__ out) {
    __shared__ float sm[8][52];
    const int row  = blockIdx.x;
    const int wid  = threadIdx.x >> 5;
    const int lane = threadIdx.x & 31;
    const bool act = lane < 25;            // 25 lanes x float2 = 50 classes

    float2 wmax = make_float2(-1e30f, -1e30f);

    for (int d = wid; d < DIMB; d += 8) {
        const int bin = d * NNODES + row;
        int j         = g_rowptr[bin];
        const int end = g_rowptr[bin + 1];
        const int off = d * NC2 + lane * 2;

        float2 acc = make_float2(0.f, 0.f);
        for (; j + 1 < end; j += 2) {
            int2 cv0 = g_ecv[j];
            int2 cv1 = g_ecv[j + 1];
            if (act) {
                float v0 = __int_as_float(cv0.y);
                float v1 = __int_as_float(cv1.y);
                float2 s0 = __half22float2(*(const __half2*)(sup2 + (size_t)cv0.x * NW2 + off));
                float2 s1 = __half22float2(*(const __half2*)(sup2 + (size_t)cv1.x * NW2 + off));
                acc.x += v0 * s0.x + v1 * s1.x;
                acc.y += v0 * s0.y + v1 * s1.y;
            }
        }
        if (j < end && act) {
            int2 cv = g_ecv[j];
            float v = __int_as_float(cv.y);
            float2 s = __half22float2(*(const __half2*)(sup2 + (size_t)cv.x * NW2 + off));
            acc.x += v * s.x;
            acc.y += v * s.y;
        }
        if (act) {
            float2 b = *(const float2*)(b2 + d * NCLASS + lane * 2);
            wmax.x = fmaxf(wmax.x, acc.x + b.x);
            wmax.y = fmaxf(wmax.y, acc.y + b.y);
        }
    }

    if (act) {
        sm[wid][lane * 2]     = wmax.x;
        sm[wid][lane * 2 + 1] = wmax.y;
    }
    __syncthreads();

    int c = threadIdx.x;
    if (c < NCLASS) {
        float m = 0.f;                      // relu folds into the max
        #pragma unroll
        for (int ww = 0; ww < 8; ww++) m = fmaxf(m, sm[ww][c]);
        out[(size_t)row * NCLASS + c] = m;
    }
}

// ================= launch ====================================================
extern "C" void kernel_launch(void* const* d_in, const int* in_sizes, int n_in,
                              void* d_out, int out_size) {
    const float* x        = (const float*)d_in[0];
    const int*   adj_rows = (const int*)d_in[1];
    const int*   adj_cols = (const int*)d_in[2];
    const float* adj_vals = (const float*)d_in[3];
    const float* W1       = (const float*)d_in[4];
    const float* b1       = (const float*)d_in[5];
    const float* W2       = (const float*)d_in[6];
    const float* b2       = (const float*)d_in[7];
    float*       out      = (float*)d_out;

    const int E = in_sizes[1] / DIMB;

    __half *p_xh, *p_w1h, *p_w2h, *p_h1h, *p_sup1, *p_sup2;
    cudaGetSymbolAddress((void**)&p_xh,   g_xh);
    cudaGetSymbolAddress((void**)&p_w1h,  g_w1h);
    cudaGetSymbolAddress((void**)&p_w2h,  g_w2h);
    cudaGetSymbolAddress((void**)&p_sup1, g_sup1);
    cudaGetSymbolAddress((void**)&p_h1h,  g_h1h);
    cudaGetSymbolAddress((void**)&p_sup2, g_sup2);

    const dim3 egrid((E + 255) / 256, DIMB);
    const int mTiles = (NNODES + 127) / 128;

    // --- prep + GEMM1 first (keeps h_mma_kernel at ncu's captured index) -----
    cvt_x_kernel<<<(NNODES * KPAD1 / 4 + 255) / 256, 256>>>(x, p_xh);
    repack1_kernel<<<(HCAT * KPAD1 + 255) / 256, 256>>>(W1, p_w1h);
    repack2_kernel<<<(NW2 * HCAT + 255) / 256, 256>>>(W2, p_w2h);
    h_mma_kernel<KPAD1, HCAT>
        <<<dim3((HCAT + 127) / 128, mTiles), 256>>>(p_xh, p_w1h, p_sup1);

    // --- CSR build -----------------------------------------------------------
    zero_cnt_kernel<<<(BTOT + 255) / 256, 256>>>();
    hist_kernel<<<egrid, 256>>>(adj_rows, E);
    scan1_kernel<<<SCAN_BLKS, 1024>>>();
    scan2_kernel<<<1, 1024>>>();
    scan3_kernel<<<SCAN_BLKS, 1024>>>(DIMB * E);
    scatter_kernel<<<egrid, 256>>>(adj_rows, adj_cols, adj_vals, E);

    // --- layer 1 spmm (fused bias/relu -> fp16) ------------------------------
    spmm1_csr_kernel<<<dim3(NNODES / 8, DIMB), 256>>>(p_sup1, b1, p_h1h);

    // --- layer 2: fp16 GEMM + fused spmm/bias/relu/max -----------------------
    h_mma_kernel<HCAT, NW2>
        <<<dim3((NW2 + 127) / 128, mTiles), 256>>>(p_h1h, p_w2h, p_sup2);
    spmm2_fused_kernel<<<NNODES, 256>>>(p_sup2, b2, out);
}

// round 13
// speedup vs baseline: 1.0646x; 1.0072x over previous
#include <cuda_runtime.h>
#include <cuda_fp16.h>
#include <cstdint>
#include <cstdio>

#define DIMB   25
#define NNODES 20000
#define NFEAT  300
#define KPAD1  320            // NFEAT padded to multiple of 64
#define NHID   64
#define NCLASS 50
#define NC2    52             // NCLASS padded to 52
#define HCAT   (DIMB * NHID)  // 1600 (K of layer-2 GEMM, %64==0)
#define NW2    (DIMB * NC2)   // 1300
#define EDGES  320000
#define BTOT   (DIMB * NNODES)
#define SCAN_BLKS ((BTOT + 1023) / 1024)

// ---------------- scratch (static device memory; no allocs allowed) ----------
__device__ __half g_xh  [(size_t)NNODES * KPAD1];
__device__ __half g_w1h [(size_t)HCAT * KPAD1];
__device__ __half g_w2h [(size_t)NW2 * HCAT];
__device__ __half g_sup1[(size_t)NNODES * HCAT];
__device__ __half g_h1h [(size_t)NNODES * HCAT];
__device__ __half g_sup2[(size_t)NNODES * NW2];
// CSR build
__device__ int   g_cnt   [BTOT];
__device__ int   g_rowptr[BTOT + 1];
__device__ int   g_bsum  [1024];
__device__ int2  g_ecv   [(size_t)DIMB * EDGES];

// ---------------- helpers ----------------------------------------------------
__device__ __forceinline__ void mma_f16(float& c0, float& c1, float& c2, float& c3,
                                        uint32_t a0, uint32_t a1, uint32_t a2, uint32_t a3,
                                        uint32_t b0, uint32_t b1) {
    asm volatile("mma.sync.aligned.m16n8k16.row.col.f32.f16.f16.f32 "
                 "{%0,%1,%2,%3}, {%4,%5,%6,%7}, {%8,%9}, {%0,%1,%2,%3};"
                 : "+f"(c0), "+f"(c1), "+f"(c2), "+f"(c3)
                 : "r"(a0), "r"(a1), "r"(a2), "r"(a3), "r"(b0), "r"(b1));
}

__device__ __forceinline__ void ldm_x4(uint32_t& r0, uint32_t& r1,
                                       uint32_t& r2, uint32_t& r3, const void* p) {
    uint32_t addr = (uint32_t)__cvta_generic_to_shared(p);
    asm volatile("ldmatrix.sync.aligned.m8n8.x4.shared.b16 {%0,%1,%2,%3}, [%4];"
                 : "=r"(r0), "=r"(r1), "=r"(r2), "=r"(r3) : "r"(addr));
}

// ================= prep ======================================================
__global__ void cvt_x_kernel(const float* __restrict__ x, __half* __restrict__ xh) {
    size_t i = (size_t)blockIdx.x * blockDim.x + threadIdx.x;
    if (i >= (size_t)NNODES * KPAD1 / 4) return;
    int n   = (int)(i / (KPAD1 / 4));
    int col = ((int)(i % (KPAD1 / 4))) * 4;
    __half2 lo = __floats2half2_rn(0.f, 0.f), hi = lo;
    if (col < NFEAT) {
        float4 v = *(const float4*)(x + (size_t)n * NFEAT + col);
        lo = __floats2half2_rn(v.x, v.y);
        hi = __floats2half2_rn(v.z, v.w);
    }
    *(uint2*)(xh + i * 4) = make_uint2(*(uint32_t*)&lo, *(uint32_t*)&hi);
}

__global__ void repack1_kernel(const float* __restrict__ W1, __half* __restrict__ B1) {
    int i = blockIdx.x * blockDim.x + threadIdx.x;
    if (i >= HCAT * KPAD1) return;
    int n = i / KPAD1, k = i - n * KPAD1;
    int d = n >> 6, h = n & 63;
    B1[i] = (k < NFEAT) ? __float2half_rn(W1[((size_t)d * NFEAT + k) * NHID + h])
                        : __float2half_rn(0.f);
}

__global__ void repack2_kernel(const float* __restrict__ W2, __half* __restrict__ B2) {
    int i = blockIdx.x * blockDim.x + threadIdx.x;
    if (i >= NW2 * HCAT) return;
    int n = i / HCAT, k = i - n * HCAT;
    int d = n / NC2, c = n - d * NC2;
    B2[i] = (c < NCLASS) ? __float2half_rn(W2[((size_t)d * HCAT + k) * NCLASS + c])
                         : __float2half_rn(0.f);
}

// ================= fp16 tensor-core GEMM =====================================
// C (NNODES x NTOT, fp16) = A (NNODES x KPAD) * Bt (NTOT x KPAD)^T.
// BM=BN=128, BK=64, 8 warps 2(m)x4(n), warp tile 64x32, m16n8k16.
// Single-buffered SMEM + register prefetch; ldmatrix fragments; 2 CTAs/SM.
template <int KPAD, int NTOT>
__global__ void __launch_bounds__(256, 2)
h_mma_kernel(const __half* __restrict__ A, const __half* __restrict__ Bt,
             __half* __restrict__ C) {
    constexpr int BK = 64;
    constexpr int KT = KPAD / BK;
    __shared__ __half As[128][72];
    __shared__ __half Bs[128][72];

    const int col0 = blockIdx.x * 128;
    const int m0   = blockIdx.y * 128;

    const int tid  = threadIdx.x;
    const int w    = tid >> 5;
    const int lane = tid & 31;
    const int g    = lane >> 2;
    const int tig  = lane & 3;
    const int wm   = (w & 1) * 64;
    const int wn   = (w >> 1) * 32;

    float acc[4][4][4];
    #pragma unroll
    for (int mt = 0; mt < 4; mt++)
        #pragma unroll
        for (int nt = 0; nt < 4; nt++)
            #pragma unroll
            for (int i = 0; i < 4; i++) acc[mt][nt][i] = 0.f;

    uint4 aS[4], bS[4];
    const uint4 z4 = make_uint4(0, 0, 0, 0);

    auto loadT = [&](int k0) {
        #pragma unroll
        for (int j = 0; j < 4; j++) {
            int id = tid + j * 256;
            int r  = id >> 3;
            int c8 = (id & 7) * 8;
            int gr = m0 + r;
            aS[j] = (gr < NNODES) ? *(const uint4*)(A + (size_t)gr * KPAD + k0 + c8) : z4;
            int gn = col0 + r;
            bS[j] = (gn < NTOT) ? *(const uint4*)(Bt + (size_t)gn * KPAD + k0 + c8) : z4;
        }
    };
    auto storeT = [&]() {
        #pragma unroll
        for (int j = 0; j < 4; j++) {
            int id = tid + j * 256;
            int r  = id >> 3;
            int c8 = (id & 7) * 8;
            *(uint4*)&As[r][c8] = aS[j];
            *(uint4*)&Bs[r][c8] = bS[j];
        }
    };

    loadT(0);

    for (int t = 0; t < KT; t++) {
        storeT();
        __syncthreads();
        if (t + 1 < KT) loadT((t + 1) * BK);

        #pragma unroll
        for (int half = 0; half < 2; half++) {
            const int kh = half * 32;
            uint32_t bq[4][4];
            #pragma unroll
            for (int nt = 0; nt < 4; nt++)
                ldm_x4(bq[nt][0], bq[nt][1], bq[nt][2], bq[nt][3],
                       &Bs[wn + nt * 8 + (lane & 7)][kh + ((lane >> 3) << 3)]);

            #pragma unroll
            for (int ks = 0; ks < 2; ks++) {
                const int k = kh + ks * 16;
                uint32_t aq[4][4];
                #pragma unroll
                for (int mt = 0; mt < 4; mt++)
                    ldm_x4(aq[mt][0], aq[mt][1], aq[mt][2], aq[mt][3],
                           &As[wm + mt * 16 + (lane & 15)][k + ((lane >> 4) << 3)]);
                #pragma unroll
                for (int mt = 0; mt < 4; mt++)
                    #pragma unroll
                    for (int nt = 0; nt < 4; nt++)
                        mma_f16(acc[mt][nt][0], acc[mt][nt][1],
                                acc[mt][nt][2], acc[mt][nt][3],
                                aq[mt][0], aq[mt][1], aq[mt][2], aq[mt][3],
                                bq[nt][ks * 2], bq[nt][ks * 2 + 1]);
            }
        }
        __syncthreads();
    }

    #pragma unroll
    for (int mt = 0; mt < 4; mt++) {
        int gr0 = m0 + wm + mt * 16 + g;
        #pragma unroll
        for (int nt = 0; nt < 4; nt++) {
            int gc = col0 + wn + nt * 8 + tig * 2;
            if (gc + 1 >= NTOT) continue;
            if (gr0 < NNODES)
                *(__half2*)(C + (size_t)gr0 * NTOT + gc) =
                    __floats2half2_rn(acc[mt][nt][0], acc[mt][nt][1]);
            if (gr0 + 8 < NNODES)
                *(__half2*)(C + (size_t)(gr0 + 8) * NTOT + gc) =
                    __floats2half2_rn(acc[mt][nt][2], acc[mt][nt][3]);
        }
    }
}

// ================= CSR construction ==========================================
__global__ void zero_cnt_kernel() {
    int i = blockIdx.x * blockDim.x + threadIdx.x;
    if (i < BTOT) g_cnt[i] = 0;
}

__global__ void hist_kernel(const int* __restrict__ rows, int E) {
    const int d = blockIdx.y;
    int e = blockIdx.x * blockDim.x + threadIdx.x;
    if (e >= E) return;
    atomicAdd(&g_cnt[d * NNODES + rows[(size_t)d * E + e]], 1);
}

__global__ void scan1_kernel() {
    __shared__ int sh[1024];
    int i = blockIdx.x * 1024 + threadIdx.x;
    int v = (i < BTOT) ? g_cnt[i] : 0;
    sh[threadIdx.x] = v;
    __syncthreads();
    #pragma unroll
    for (int off = 1; off < 1024; off <<= 1) {
        int t = (threadIdx.x >= off) ? sh[threadIdx.x - off] : 0;
        __syncthreads();
        sh[threadIdx.x] += t;
        __syncthreads();
    }
    if (i < BTOT) g_rowptr[i] = sh[threadIdx.x] - v;
    if (threadIdx.x == 1023) g_bsum[blockIdx.x] = sh[1023];
}

__global__ void scan2_kernel() {
    __shared__ int sh[1024];
    int v = (threadIdx.x < SCAN_BLKS) ? g_bsum[threadIdx.x] : 0;
    sh[threadIdx.x] = v;
    __syncthreads();
    #pragma unroll
    for (int off = 1; off < 1024; off <<= 1) {
        int t = (threadIdx.x >= off) ? sh[threadIdx.x - off] : 0;
        __syncthreads();
        sh[threadIdx.x] += t;
        __syncthreads();
    }
    if (threadIdx.x < SCAN_BLKS) g_bsum[threadIdx.x] = sh[threadIdx.x] - v;
}

__global__ void scan3_kernel(int total) {
    int i = blockIdx.x * 1024 + threadIdx.x;
    if (i < BTOT) {
        g_rowptr[i] += g_bsum[blockIdx.x];
        g_cnt[i] = 0;
    }
    if (i == 0) g_rowptr[BTOT] = total;
}

__global__ void scatter_kernel(const int* __restrict__ rows,
                               const int* __restrict__ cols,
                               const float* __restrict__ vals, int E) {
    const int d = blockIdx.y;
    int e = blockIdx.x * blockDim.x + threadIdx.x;
    if (e >= E) return;
    size_t eo = (size_t)d * E + e;
    int bin = d * NNODES + rows[eo];
    int pos = g_rowptr[bin] + atomicAdd(&g_cnt[bin], 1);
    g_ecv[pos] = make_int2(cols[eo], __float_as_int(vals[eo]));
}

// ================= CSR SpMM layer 1 (fp16 gather, fp32 acc, -> fp16) =========
__global__ void __launch_bounds__(256)
spmm1_csr_kernel(const __half* __restrict__ sup1, const float* __restrict__ b1,
                 __half* __restrict__ h1h) {
    const int d    = blockIdx.y;
    const int wid  = threadIdx.x >> 5;
    const int lane = threadIdx.x & 31;
    const int row  = blockIdx.x * 8 + wid;
    if (row >= NNODES) return;

    const int bin = d * NNODES + row;
    int j         = g_rowptr[bin];
    const int end = g_rowptr[bin + 1];
    const int off = d * NHID + lane * 2;

    float2 acc = make_float2(0.f, 0.f);
    for (; j + 1 < end; j += 2) {
        int2 cv0 = g_ecv[j];
        int2 cv1 = g_ecv[j + 1];
        float v0 = __int_as_float(cv0.y);
        float v1 = __int_as_float(cv1.y);
        float2 s0 = __half22float2(*(const __half2*)(sup1 + (size_t)cv0.x * HCAT + off));
        float2 s1 = __half22float2(*(const __half2*)(sup1 + (size_t)cv1.x * HCAT + off));
        acc.x += v0 * s0.x + v1 * s1.x;
        acc.y += v0 * s0.y + v1 * s1.y;
    }
    if (j < end) {
        int2 cv = g_ecv[j];
        float v = __int_as_float(cv.y);
        float2 s = __half22float2(*(const __half2*)(sup1 + (size_t)cv.x * HCAT + off));
        acc.x += v * s.x;
        acc.y += v * s.y;
    }

    float2 b = *(const float2*)(b1 + off);
    acc.x = fmaxf(acc.x + b.x, 0.f);
    acc.y = fmaxf(acc.y + b.y, 0.f);
    *(__half2*)(h1h + (size_t)row * HCAT + off) = __floats2half2_rn(acc.x, acc.y);
}

// ================= fused CSR SpMM layer 2 + bias + relu + max-pool ===========
__global__ void __launch_bounds__(256)
spmm2_fused_kernel(const __half* __restrict__ sup2, const float* __restrict__ b2,
                   float* __restrict__ out) {
    __shared__ float sm[8][52];
    const int row  = blockIdx.x;
    const int wid  = threadIdx.x >> 5;
    const int lane = threadIdx.x & 31;
    const bool act = lane < 25;            // 25 lanes x float2 = 50 classes

    float2 wmax = make_float2(-1e30f, -1e30f);

    for (int d = wid; d < DIMB; d += 8) {
        const int bin = d * NNODES + row;
        int j         = g_rowptr[bin];
        const int end = g_rowptr[bin + 1];
        const int off = d * NC2 + lane * 2;

        float2 acc = make_float2(0.f, 0.f);
        for (; j + 1 < end; j += 2) {
            int2 cv0 = g_ecv[j];
            int2 cv1 = g_ecv[j + 1];
            if (act) {
                float v0 = __int_as_float(cv0.y);
                float v1 = __int_as_float(cv1.y);
                float2 s0 = __half22float2(*(const __half2*)(sup2 + (size_t)cv0.x * NW2 + off));
                float2 s1 = __half22float2(*(const __half2*)(sup2 + (size_t)cv1.x * NW2 + off));
                acc.x += v0 * s0.x + v1 * s1.x;
                acc.y += v0 * s0.y + v1 * s1.y;
            }
        }
        if (j < end && act) {
            int2 cv = g_ecv[j];
            float v = __int_as_float(cv.y);
            float2 s = __half22float2(*(const __half2*)(sup2 + (size_t)cv.x * NW2 + off));
            acc.x += v * s.x;
            acc.y += v * s.y;
        }
        if (act) {
            float2 b = *(const float2*)(b2 + d * NCLASS + lane * 2);
            wmax.x = fmaxf(wmax.x, acc.x + b.x);
            wmax.y = fmaxf(wmax.y, acc.y + b.y);
        }
    }

    if (act) {
        sm[wid][lane * 2]     = wmax.x;
        sm[wid][lane * 2 + 1] = wmax.y;
    }
    __syncthreads();

    int c = threadIdx.x;
    if (c < NCLASS) {
        float m = 0.f;                      // relu folds into the max
        #pragma unroll
        for (int ww = 0; ww < 8; ww++) m = fmaxf(m, sm[ww][c]);
        out[(size_t)row * NCLASS + c] = m;
    }
}

// ================= launch ====================================================
extern "C" void kernel_launch(void* const* d_in, const int* in_sizes, int n_in,
                              void* d_out, int out_size) {
    const float* x        = (const float*)d_in[0];
    const int*   adj_rows = (const int*)d_in[1];
    const int*   adj_cols = (const int*)d_in[2];
    const float* adj_vals = (const float*)d_in[3];
    const float* W1       = (const float*)d_in[4];
    const float* b1       = (const float*)d_in[5];
    const float* W2       = (const float*)d_in[6];
    const float* b2       = (const float*)d_in[7];
    float*       out      = (float*)d_out;

    const int E = in_sizes[1] / DIMB;

    __half *p_xh, *p_w1h, *p_w2h, *p_h1h, *p_sup1, *p_sup2;
    cudaGetSymbolAddress((void**)&p_xh,   g_xh);
    cudaGetSymbolAddress((void**)&p_w1h,  g_w1h);
    cudaGetSymbolAddress((void**)&p_w2h,  g_w2h);
    cudaGetSymbolAddress((void**)&p_sup1, g_sup1);
    cudaGetSymbolAddress((void**)&p_h1h,  g_h1h);
    cudaGetSymbolAddress((void**)&p_sup2, g_sup2);

    const dim3 egrid((E + 255) / 256, DIMB);
    const int mTiles = (NNODES + 127) / 128;

    // Fork a side stream so the CSR build overlaps prep + GEMM1 in the
    // captured graph. Objects are created per call (not freed: no device
    // memory involved; kernel_launch runs only a handful of times).
    cudaStream_t s2;
    cudaStreamCreateWithFlags(&s2, cudaStreamNonBlocking);
    cudaEvent_t eFork, eJoin;
    cudaEventCreateWithFlags(&eFork, cudaEventDisableTiming);
    cudaEventCreateWithFlags(&eJoin, cudaEventDisableTiming);

    cudaEventRecord(eFork, 0);
    cudaStreamWaitEvent(s2, eFork, 0);

    // --- branch A (s2): CSR build -------------------------------------------
    zero_cnt_kernel<<<(BTOT + 255) / 256, 256, 0, s2>>>();
    hist_kernel<<<egrid, 256, 0, s2>>>(adj_rows, E);
    scan1_kernel<<<SCAN_BLKS, 1024, 0, s2>>>();
    scan2_kernel<<<1, 1024, 0, s2>>>();
    scan3_kernel<<<SCAN_BLKS, 1024, 0, s2>>>(DIMB * E);
    scatter_kernel<<<egrid, 256, 0, s2>>>(adj_rows, adj_cols, adj_vals, E);
    cudaEventRecord(eJoin, s2);

    // --- branch B (main stream): prep + GEMM1 --------------------------------
    cvt_x_kernel<<<(NNODES * KPAD1 / 4 + 255) / 256, 256>>>(x, p_xh);
    repack1_kernel<<<(HCAT * KPAD1 + 255) / 256, 256>>>(W1, p_w1h);
    repack2_kernel<<<(NW2 * HCAT + 255) / 256, 256>>>(W2, p_w2h);
    h_mma_kernel<KPAD1, HCAT>
        <<<dim3((HCAT + 127) / 128, mTiles), 256>>>(p_xh, p_w1h, p_sup1);

    // --- join: spmm1 needs both GEMM1 output and the CSR ---------------------
    cudaStreamWaitEvent(0, eJoin, 0);

    spmm1_csr_kernel<<<dim3(NNODES / 8, DIMB), 256>>>(p_sup1, b1, p_h1h);

    h_mma_kernel<HCAT, NW2>
        <<<dim3((NW2 + 127) / 128, mTiles), 256>>>(p_h1h, p_w2h, p_sup2);
    spmm2_fused_kernel<<<NNODES, 256>>>(p_sup2, b2, out);
}

// round 14
// speedup vs baseline: 1.0883x; 1.0223x over previous
#include <cuda_runtime.h>
#include <cuda_fp16.h>
#include <cstdint>
#include <cstdio>

#define DIMB   25
#define NNODES 20000
#define NFEAT  300
#define KPAD1  320            // NFEAT padded to multiple of 64
#define NHID   64
#define NCLASS 50
#define NC2    52             // NCLASS padded to 52
#define HCAT   (DIMB * NHID)  // 1600 (K of layer-2 GEMM, %64==0)
#define NW2    (DIMB * NC2)   // 1300
#define EDGES  320000
#define BTOT   (DIMB * NNODES)
#define SCAN_BLKS ((BTOT + 1023) / 1024)

// ---------------- scratch (static device memory; no allocs allowed) ----------
__device__ __half g_xh  [(size_t)NNODES * KPAD1];
__device__ __half g_w1h [(size_t)HCAT * KPAD1];
__device__ __half g_w2h [(size_t)NW2 * HCAT];
__device__ __half g_sup1[(size_t)NNODES * HCAT];
__device__ __half g_h1h [(size_t)NNODES * HCAT];
__device__ __half g_sup2[(size_t)NNODES * NW2];
// CSR build
__device__ int   g_cnt   [BTOT];
__device__ int   g_rowptr[BTOT + 1];
__device__ int   g_bsum  [1024];
__device__ int2  g_ecv   [(size_t)DIMB * EDGES];

// ---------------- helpers ----------------------------------------------------
__device__ __forceinline__ void mma_f16(float& c0, float& c1, float& c2, float& c3,
                                        uint32_t a0, uint32_t a1, uint32_t a2, uint32_t a3,
                                        uint32_t b0, uint32_t b1) {
    asm volatile("mma.sync.aligned.m16n8k16.row.col.f32.f16.f16.f32 "
                 "{%0,%1,%2,%3}, {%4,%5,%6,%7}, {%8,%9}, {%0,%1,%2,%3};"
                 : "+f"(c0), "+f"(c1), "+f"(c2), "+f"(c3)
                 : "r"(a0), "r"(a1), "r"(a2), "r"(a3), "r"(b0), "r"(b1));
}

__device__ __forceinline__ void ldm_x4(uint32_t& r0, uint32_t& r1,
                                       uint32_t& r2, uint32_t& r3, const void* p) {
    uint32_t addr = (uint32_t)__cvta_generic_to_shared(p);
    asm volatile("ldmatrix.sync.aligned.m8n8.x4.shared.b16 {%0,%1,%2,%3}, [%4];"
                 : "=r"(r0), "=r"(r1), "=r"(r2), "=r"(r3) : "r"(addr));
}

// ================= prep ======================================================
__global__ void cvt_x_kernel(const float* __restrict__ x, __half* __restrict__ xh) {
    size_t i = (size_t)blockIdx.x * blockDim.x + threadIdx.x;
    if (i >= (size_t)NNODES * KPAD1 / 4) return;
    int n   = (int)(i / (KPAD1 / 4));
    int col = ((int)(i % (KPAD1 / 4))) * 4;
    __half2 lo = __floats2half2_rn(0.f, 0.f), hi = lo;
    if (col < NFEAT) {
        float4 v = *(const float4*)(x + (size_t)n * NFEAT + col);
        lo = __floats2half2_rn(v.x, v.y);
        hi = __floats2half2_rn(v.z, v.w);
    }
    *(uint2*)(xh + i * 4) = make_uint2(*(uint32_t*)&lo, *(uint32_t*)&hi);
}

__global__ void repack1_kernel(const float* __restrict__ W1, __half* __restrict__ B1) {
    int i = blockIdx.x * blockDim.x + threadIdx.x;
    if (i >= HCAT * KPAD1) return;
    int n = i / KPAD1, k = i - n * KPAD1;
    int d = n >> 6, h = n & 63;
    B1[i] = (k < NFEAT) ? __float2half_rn(W1[((size_t)d * NFEAT + k) * NHID + h])
                        : __float2half_rn(0.f);
}

__global__ void repack2_kernel(const float* __restrict__ W2, __half* __restrict__ B2) {
    int i = blockIdx.x * blockDim.x + threadIdx.x;
    if (i >= NW2 * HCAT) return;
    int n = i / HCAT, k = i - n * HCAT;
    int d = n / NC2, c = n - d * NC2;
    B2[i] = (c < NCLASS) ? __float2half_rn(W2[((size_t)d * HCAT + k) * NCLASS + c])
                         : __float2half_rn(0.f);
}

// ================= fp16 tensor-core GEMM =====================================
// C (NNODES x NTOT, fp16) = A (NNODES x KPAD) * Bt (NTOT x KPAD)^T.
// BM=BN=128, BK=64, 8 warps 2(m)x4(n), warp tile 64x32, m16n8k16.
// Single-buffered SMEM + register prefetch; ldmatrix fragments; 2 CTAs/SM.
template <int KPAD, int NTOT>
__global__ void __launch_bounds__(256, 2)
h_mma_kernel(const __half* __restrict__ A, const __half* __restrict__ Bt,
             __half* __restrict__ C) {
    constexpr int BK = 64;
    constexpr int KT = KPAD / BK;
    __shared__ __half As[128][72];
    __shared__ __half Bs[128][72];

    const int col0 = blockIdx.x * 128;
    const int m0   = blockIdx.y * 128;

    const int tid  = threadIdx.x;
    const int w    = tid >> 5;
    const int lane = tid & 31;
    const int g    = lane >> 2;
    const int tig  = lane & 3;
    const int wm   = (w & 1) * 64;
    const int wn   = (w >> 1) * 32;

    float acc[4][4][4];
    #pragma unroll
    for (int mt = 0; mt < 4; mt++)
        #pragma unroll
        for (int nt = 0; nt < 4; nt++)
            #pragma unroll
            for (int i = 0; i < 4; i++) acc[mt][nt][i] = 0.f;

    uint4 aS[4], bS[4];
    const uint4 z4 = make_uint4(0, 0, 0, 0);

    auto loadT = [&](int k0) {
        #pragma unroll
        for (int j = 0; j < 4; j++) {
            int id = tid + j * 256;
            int r  = id >> 3;
            int c8 = (id & 7) * 8;
            int gr = m0 + r;
            aS[j] = (gr < NNODES) ? *(const uint4*)(A + (size_t)gr * KPAD + k0 + c8) : z4;
            int gn = col0 + r;
            bS[j] = (gn < NTOT) ? *(const uint4*)(Bt + (size_t)gn * KPAD + k0 + c8) : z4;
        }
    };
    auto storeT = [&]() {
        #pragma unroll
        for (int j = 0; j < 4; j++) {
            int id = tid + j * 256;
            int r  = id >> 3;
            int c8 = (id & 7) * 8;
            *(uint4*)&As[r][c8] = aS[j];
            *(uint4*)&Bs[r][c8] = bS[j];
        }
    };

    loadT(0);

    for (int t = 0; t < KT; t++) {
        storeT();
        __syncthreads();
        if (t + 1 < KT) loadT((t + 1) * BK);

        #pragma unroll
        for (int half = 0; half < 2; half++) {
            const int kh = half * 32;
            uint32_t bq[4][4];
            #pragma unroll
            for (int nt = 0; nt < 4; nt++)
                ldm_x4(bq[nt][0], bq[nt][1], bq[nt][2], bq[nt][3],
                       &Bs[wn + nt * 8 + (lane & 7)][kh + ((lane >> 3) << 3)]);

            #pragma unroll
            for (int ks = 0; ks < 2; ks++) {
                const int k = kh + ks * 16;
                uint32_t aq[4][4];
                #pragma unroll
                for (int mt = 0; mt < 4; mt++)
                    ldm_x4(aq[mt][0], aq[mt][1], aq[mt][2], aq[mt][3],
                           &As[wm + mt * 16 + (lane & 15)][k + ((lane >> 4) << 3)]);
                #pragma unroll
                for (int mt = 0; mt < 4; mt++)
                    #pragma unroll
                    for (int nt = 0; nt < 4; nt++)
                        mma_f16(acc[mt][nt][0], acc[mt][nt][1],
                                acc[mt][nt][2], acc[mt][nt][3],
                                aq[mt][0], aq[mt][1], aq[mt][2], aq[mt][3],
                                bq[nt][ks * 2], bq[nt][ks * 2 + 1]);
            }
        }
        __syncthreads();
    }

    #pragma unroll
    for (int mt = 0; mt < 4; mt++) {
        int gr0 = m0 + wm + mt * 16 + g;
        #pragma unroll
        for (int nt = 0; nt < 4; nt++) {
            int gc = col0 + wn + nt * 8 + tig * 2;
            if (gc + 1 >= NTOT) continue;
            if (gr0 < NNODES)
                *(__half2*)(C + (size_t)gr0 * NTOT + gc) =
                    __floats2half2_rn(acc[mt][nt][0], acc[mt][nt][1]);
            if (gr0 + 8 < NNODES)
                *(__half2*)(C + (size_t)(gr0 + 8) * NTOT + gc) =
                    __floats2half2_rn(acc[mt][nt][2], acc[mt][nt][3]);
        }
    }
}

// ================= CSR construction ==========================================
__global__ void zero_cnt_kernel() {
    int i = blockIdx.x * blockDim.x + threadIdx.x;
    if (i < BTOT) g_cnt[i] = 0;
}

__global__ void hist_kernel(const int* __restrict__ rows, int E) {
    const int d = blockIdx.y;
    int e = blockIdx.x * blockDim.x + threadIdx.x;
    if (e >= E) return;
    atomicAdd(&g_cnt[d * NNODES + rows[(size_t)d * E + e]], 1);
}

__global__ void scan1_kernel() {
    __shared__ int sh[1024];
    int i = blockIdx.x * 1024 + threadIdx.x;
    int v = (i < BTOT) ? g_cnt[i] : 0;
    sh[threadIdx.x] = v;
    __syncthreads();
    #pragma unroll
    for (int off = 1; off < 1024; off <<= 1) {
        int t = (threadIdx.x >= off) ? sh[threadIdx.x - off] : 0;
        __syncthreads();
        sh[threadIdx.x] += t;
        __syncthreads();
    }
    if (i < BTOT) g_rowptr[i] = sh[threadIdx.x] - v;
    if (threadIdx.x == 1023) g_bsum[blockIdx.x] = sh[1023];
}

__global__ void scan2_kernel() {
    __shared__ int sh[1024];
    int v = (threadIdx.x < SCAN_BLKS) ? g_bsum[threadIdx.x] : 0;
    sh[threadIdx.x] = v;
    __syncthreads();
    #pragma unroll
    for (int off = 1; off < 1024; off <<= 1) {
        int t = (threadIdx.x >= off) ? sh[threadIdx.x - off] : 0;
        __syncthreads();
        sh[threadIdx.x] += t;
        __syncthreads();
    }
    if (threadIdx.x < SCAN_BLKS) g_bsum[threadIdx.x] = sh[threadIdx.x] - v;
}

__global__ void scan3_kernel(int total) {
    int i = blockIdx.x * 1024 + threadIdx.x;
    if (i < BTOT) {
        g_rowptr[i] += g_bsum[blockIdx.x];
        g_cnt[i] = 0;
    }
    if (i == 0) g_rowptr[BTOT] = total;
}

__global__ void scatter_kernel(const int* __restrict__ rows,
                               const int* __restrict__ cols,
                               const float* __restrict__ vals, int E) {
    const int d = blockIdx.y;
    int e = blockIdx.x * blockDim.x + threadIdx.x;
    if (e >= E) return;
    size_t eo = (size_t)d * E + e;
    int bin = d * NNODES + rows[eo];
    int pos = g_rowptr[bin] + atomicAdd(&g_cnt[bin], 1);
    g_ecv[pos] = make_int2(cols[eo], __float_as_int(vals[eo]));
}

// ================= CSR SpMM layer 1 (4-edge unroll for MLP) ==================
__global__ void __launch_bounds__(256)
spmm1_csr_kernel(const __half* __restrict__ sup1, const float* __restrict__ b1,
                 __half* __restrict__ h1h) {
    const int d    = blockIdx.y;
    const int wid  = threadIdx.x >> 5;
    const int lane = threadIdx.x & 31;
    const int row  = blockIdx.x * 8 + wid;
    if (row >= NNODES) return;

    const int bin = d * NNODES + row;
    int j         = g_rowptr[bin];
    const int end = g_rowptr[bin + 1];
    const int off = d * NHID + lane * 2;

    float2 acc = make_float2(0.f, 0.f);
    for (; j + 3 < end; j += 4) {
        int2 cv0 = g_ecv[j];
        int2 cv1 = g_ecv[j + 1];
        int2 cv2 = g_ecv[j + 2];
        int2 cv3 = g_ecv[j + 3];
        float2 s0 = __half22float2(*(const __half2*)(sup1 + (size_t)cv0.x * HCAT + off));
        float2 s1 = __half22float2(*(const __half2*)(sup1 + (size_t)cv1.x * HCAT + off));
        float2 s2 = __half22float2(*(const __half2*)(sup1 + (size_t)cv2.x * HCAT + off));
        float2 s3 = __half22float2(*(const __half2*)(sup1 + (size_t)cv3.x * HCAT + off));
        float v0 = __int_as_float(cv0.y);
        float v1 = __int_as_float(cv1.y);
        float v2 = __int_as_float(cv2.y);
        float v3 = __int_as_float(cv3.y);
        acc.x += v0 * s0.x + v1 * s1.x + v2 * s2.x + v3 * s3.x;
        acc.y += v0 * s0.y + v1 * s1.y + v2 * s2.y + v3 * s3.y;
    }
    for (; j < end; j++) {
        int2 cv = g_ecv[j];
        float v = __int_as_float(cv.y);
        float2 s = __half22float2(*(const __half2*)(sup1 + (size_t)cv.x * HCAT + off));
        acc.x += v * s.x;
        acc.y += v * s.y;
    }

    float2 b = *(const float2*)(b1 + off);
    acc.x = fmaxf(acc.x + b.x, 0.f);
    acc.y = fmaxf(acc.y + b.y, 0.f);
    *(__half2*)(h1h + (size_t)row * HCAT + off) = __floats2half2_rn(acc.x, acc.y);
}

// ================= fused CSR SpMM layer 2 + bias + relu + max-pool ===========
__global__ void __launch_bounds__(256)
spmm2_fused_kernel(const __half* __restrict__ sup2, const float* __restrict__ b2,
                   float* __restrict__ out) {
    __shared__ float sm[8][52];
    const int row  = blockIdx.x;
    const int wid  = threadIdx.x >> 5;
    const int lane = threadIdx.x & 31;
    const bool act = lane < 25;            // 25 lanes x float2 = 50 classes

    float2 wmax = make_float2(-1e30f, -1e30f);

    for (int d = wid; d < DIMB; d += 8) {
        const int bin = d * NNODES + row;
        int j         = g_rowptr[bin];
        const int end = g_rowptr[bin + 1];
        const int off = d * NC2 + lane * 2;

        float2 acc = make_float2(0.f, 0.f);
        for (; j + 3 < end; j += 4) {
            int2 cv0 = g_ecv[j];
            int2 cv1 = g_ecv[j + 1];
            int2 cv2 = g_ecv[j + 2];
            int2 cv3 = g_ecv[j + 3];
            if (act) {
                float2 s0 = __half22float2(*(const __half2*)(sup2 + (size_t)cv0.x * NW2 + off));
                float2 s1 = __half22float2(*(const __half2*)(sup2 + (size_t)cv1.x * NW2 + off));
                float2 s2 = __half22float2(*(const __half2*)(sup2 + (size_t)cv2.x * NW2 + off));
                float2 s3 = __half22float2(*(const __half2*)(sup2 + (size_t)cv3.x * NW2 + off));
                float v0 = __int_as_float(cv0.y);
                float v1 = __int_as_float(cv1.y);
                float v2 = __int_as_float(cv2.y);
                float v3 = __int_as_float(cv3.y);
                acc.x += v0 * s0.x + v1 * s1.x + v2 * s2.x + v3 * s3.x;
                acc.y += v0 * s0.y + v1 * s1.y + v2 * s2.y + v3 * s3.y;
            }
        }
        for (; j < end; j++) {
            int2 cv = g_ecv[j];
            if (act) {
                float v = __int_as_float(cv.y);
                float2 s = __half22float2(*(const __half2*)(sup2 + (size_t)cv.x * NW2 + off));
                acc.x += v * s.x;
                acc.y += v * s.y;
            }
        }
        if (act) {
            float2 b = *(const float2*)(b2 + d * NCLASS + lane * 2);
            wmax.x = fmaxf(wmax.x, acc.x + b.x);
            wmax.y = fmaxf(wmax.y, acc.y + b.y);
        }
    }

    if (act) {
        sm[wid][lane * 2]     = wmax.x;
        sm[wid][lane * 2 + 1] = wmax.y;
    }
    __syncthreads();

    int c = threadIdx.x;
    if (c < NCLASS) {
        float m = 0.f;                      // relu folds into the max
        #pragma unroll
        for (int ww = 0; ww < 8; ww++) m = fmaxf(m, sm[ww][c]);
        out[(size_t)row * NCLASS + c] = m;
    }
}

// ================= launch ====================================================
extern "C" void kernel_launch(void* const* d_in, const int* in_sizes, int n_in,
                              void* d_out, int out_size) {
    const float* x        = (const float*)d_in[0];
    const int*   adj_rows = (const int*)d_in[1];
    const int*   adj_cols = (const int*)d_in[2];
    const float* adj_vals = (const float*)d_in[3];
    const float* W1       = (const float*)d_in[4];
    const float* b1       = (const float*)d_in[5];
    const float* W2       = (const float*)d_in[6];
    const float* b2       = (const float*)d_in[7];
    float*       out      = (float*)d_out;

    const int E = in_sizes[1] / DIMB;

    __half *p_xh, *p_w1h, *p_w2h, *p_h1h, *p_sup1, *p_sup2;
    cudaGetSymbolAddress((void**)&p_xh,   g_xh);
    cudaGetSymbolAddress((void**)&p_w1h,  g_w1h);
    cudaGetSymbolAddress((void**)&p_w2h,  g_w2h);
    cudaGetSymbolAddress((void**)&p_sup1, g_sup1);
    cudaGetSymbolAddress((void**)&p_h1h,  g_h1h);
    cudaGetSymbolAddress((void**)&p_sup2, g_sup2);

    const dim3 egrid((E + 255) / 256, DIMB);
    const int mTiles = (NNODES + 127) / 128;

    // Fork a side stream so the CSR build overlaps prep + GEMM1 in the
    // captured graph.
    cudaStream_t s2;
    cudaStreamCreateWithFlags(&s2, cudaStreamNonBlocking);
    cudaEvent_t eFork, eJoin;
    cudaEventCreateWithFlags(&eFork, cudaEventDisableTiming);
    cudaEventCreateWithFlags(&eJoin, cudaEventDisableTiming);

    cudaEventRecord(eFork, 0);
    cudaStreamWaitEvent(s2, eFork, 0);

    // --- branch A (s2): CSR build -------------------------------------------
    zero_cnt_kernel<<<(BTOT + 255) / 256, 256, 0, s2>>>();
    hist_kernel<<<egrid, 256, 0, s2>>>(adj_rows, E);
    scan1_kernel<<<SCAN_BLKS, 1024, 0, s2>>>();
    scan2_kernel<<<1, 1024, 0, s2>>>();
    scan3_kernel<<<SCAN_BLKS, 1024, 0, s2>>>(DIMB * E);
    scatter_kernel<<<egrid, 256, 0, s2>>>(adj_rows, adj_cols, adj_vals, E);
    cudaEventRecord(eJoin, s2);

    // --- branch B (main stream): prep + GEMM1 --------------------------------
    cvt_x_kernel<<<(NNODES * KPAD1 / 4 + 255) / 256, 256>>>(x, p_xh);
    repack1_kernel<<<(HCAT * KPAD1 + 255) / 256, 256>>>(W1, p_w1h);
    repack2_kernel<<<(NW2 * HCAT + 255) / 256, 256>>>(W2, p_w2h);
    h_mma_kernel<KPAD1, HCAT>
        <<<dim3((HCAT + 127) / 128, mTiles), 256>>>(p_xh, p_w1h, p_sup1);

    // --- join: spmm1 needs both GEMM1 output and the CSR ---------------------
    cudaStreamWaitEvent(0, eJoin, 0);

    spmm1_csr_kernel<<<dim3(NNODES / 8, DIMB), 256>>>(p_sup1, b1, p_h1h);

    h_mma_kernel<HCAT, NW2>
        <<<dim3((NW2 + 127) / 128, mTiles), 256>>>(p_h1h, p_w2h, p_sup2);
    spmm2_fused_kernel<<<NNODES, 256>>>(p_sup2, b2, out);
}

// round 16
// speedup vs baseline: 1.1383x; 1.0459x over previous
#include <cuda_runtime.h>
#include <cuda_fp16.h>
#include <cstdint>
#include <cstdio>

#define DIMB   25
#define NNODES 20000
#define NFEAT  300
#define KPAD1  320            // NFEAT padded to multiple of 64
#define NHID   64
#define NCLASS 50
#define NC2    52             // NCLASS padded to 52
#define HCAT   (DIMB * NHID)  // 1600 (K of layer-2 GEMM, %64==0)
#define NW2    (DIMB * NC2)   // 1300
#define EDGES  320000
#define BTOT   (DIMB * NNODES)
#define SCAN_BLKS ((BTOT + 1023) / 1024)

// ---------------- scratch (static device memory; no allocs allowed) ----------
__device__ __half g_xh  [(size_t)NNODES * KPAD1];
__device__ __half g_w1h [(size_t)HCAT * KPAD1];
__device__ __half g_w2h [(size_t)NW2 * HCAT];
__device__ __half g_sup1[(size_t)NNODES * HCAT];
__device__ __half g_h1h [(size_t)NNODES * HCAT];
__device__ __half g_sup2[(size_t)NNODES * NW2];
// CSR build
__device__ int   g_cnt   [BTOT];
__device__ int   g_rowptr[BTOT + 1];
__device__ int   g_bsum  [1024];
__device__ int2  g_ecv   [(size_t)DIMB * EDGES];

// ---------------- helpers ----------------------------------------------------
__device__ __forceinline__ void mma_f16(float& c0, float& c1, float& c2, float& c3,
                                        uint32_t a0, uint32_t a1, uint32_t a2, uint32_t a3,
                                        uint32_t b0, uint32_t b1) {
    asm volatile("mma.sync.aligned.m16n8k16.row.col.f32.f16.f16.f32 "
                 "{%0,%1,%2,%3}, {%4,%5,%6,%7}, {%8,%9}, {%0,%1,%2,%3};"
                 : "+f"(c0), "+f"(c1), "+f"(c2), "+f"(c3)
                 : "r"(a0), "r"(a1), "r"(a2), "r"(a3), "r"(b0), "r"(b1));
}

__device__ __forceinline__ void ldm_x4(uint32_t& r0, uint32_t& r1,
                                       uint32_t& r2, uint32_t& r3, const void* p) {
    uint32_t addr = (uint32_t)__cvta_generic_to_shared(p);
    asm volatile("ldmatrix.sync.aligned.m8n8.x4.shared.b16 {%0,%1,%2,%3}, [%4];"
                 : "=r"(r0), "=r"(r1), "=r"(r2), "=r"(r3) : "r"(addr));
}

// ================= prep ======================================================
__global__ void cvt_x_kernel(const float* __restrict__ x, __half* __restrict__ xh) {
    size_t i = (size_t)blockIdx.x * blockDim.x + threadIdx.x;
    if (i >= (size_t)NNODES * KPAD1 / 4) return;
    int n   = (int)(i / (KPAD1 / 4));
    int col = ((int)(i % (KPAD1 / 4))) * 4;
    __half2 lo = __floats2half2_rn(0.f, 0.f), hi = lo;
    if (col < NFEAT) {
        float4 v = *(const float4*)(x + (size_t)n * NFEAT + col);
        lo = __floats2half2_rn(v.x, v.y);
        hi = __floats2half2_rn(v.z, v.w);
    }
    *(uint2*)(xh + i * 4) = make_uint2(*(uint32_t*)&lo, *(uint32_t*)&hi);
}

__global__ void repack1_kernel(const float* __restrict__ W1, __half* __restrict__ B1) {
    int i = blockIdx.x * blockDim.x + threadIdx.x;
    if (i >= HCAT * KPAD1) return;
    int n = i / KPAD1, k = i - n * KPAD1;
    int d = n >> 6, h = n & 63;
    B1[i] = (k < NFEAT) ? __float2half_rn(W1[((size_t)d * NFEAT + k) * NHID + h])
                        : __float2half_rn(0.f);
}

__global__ void repack2_kernel(const float* __restrict__ W2, __half* __restrict__ B2) {
    int i = blockIdx.x * blockDim.x + threadIdx.x;
    if (i >= NW2 * HCAT) return;
    int n = i / HCAT, k = i - n * HCAT;
    int d = n / NC2, c = n - d * NC2;
    B2[i] = (c < NCLASS) ? __float2half_rn(W2[((size_t)d * HCAT + k) * NCLASS + c])
                         : __float2half_rn(0.f);
}

// ================= fp16 tensor-core GEMM =====================================
// C (NNODES x NTOT, fp16) = A (NNODES x KPAD) * Bt (NTOT x KPAD)^T.
// BM=BN=128, BK=64, 8 warps 2(m)x4(n), warp tile 64x32, m16n8k16.
// Single-buffered SMEM + register prefetch; ldmatrix fragments; 2 CTAs/SM.
template <int KPAD, int NTOT>
__global__ void __launch_bounds__(256, 2)
h_mma_kernel(const __half* __restrict__ A, const __half* __restrict__ Bt,
             __half* __restrict__ C) {
    constexpr int BK = 64;
    constexpr int KT = KPAD / BK;
    __shared__ __half As[128][72];
    __shared__ __half Bs[128][72];

    const int col0 = blockIdx.x * 128;
    const int m0   = blockIdx.y * 128;

    const int tid  = threadIdx.x;
    const int w    = tid >> 5;
    const int lane = tid & 31;
    const int g    = lane >> 2;
    const int tig  = lane & 3;
    const int wm   = (w & 1) * 64;
    const int wn   = (w >> 1) * 32;

    float acc[4][4][4];
    #pragma unroll
    for (int mt = 0; mt < 4; mt++)
        #pragma unroll
        for (int nt = 0; nt < 4; nt++)
            #pragma unroll
            for (int i = 0; i < 4; i++) acc[mt][nt][i] = 0.f;

    uint4 aS[4], bS[4];
    const uint4 z4 = make_uint4(0, 0, 0, 0);

    auto loadT = [&](int k0) {
        #pragma unroll
        for (int j = 0; j < 4; j++) {
            int id = tid + j * 256;
            int r  = id >> 3;
            int c8 = (id & 7) * 8;
            int gr = m0 + r;
            aS[j] = (gr < NNODES) ? *(const uint4*)(A + (size_t)gr * KPAD + k0 + c8) : z4;
            int gn = col0 + r;
            bS[j] = (gn < NTOT) ? *(const uint4*)(Bt + (size_t)gn * KPAD + k0 + c8) : z4;
        }
    };
    auto storeT = [&]() {
        #pragma unroll
        for (int j = 0; j < 4; j++) {
            int id = tid + j * 256;
            int r  = id >> 3;
            int c8 = (id & 7) * 8;
            *(uint4*)&As[r][c8] = aS[j];
            *(uint4*)&Bs[r][c8] = bS[j];
        }
    };

    loadT(0);

    for (int t = 0; t < KT; t++) {
        storeT();
        __syncthreads();
        if (t + 1 < KT) loadT((t + 1) * BK);

        #pragma unroll
        for (int half = 0; half < 2; half++) {
            const int kh = half * 32;
            uint32_t bq[4][4];
            #pragma unroll
            for (int nt = 0; nt < 4; nt++)
                ldm_x4(bq[nt][0], bq[nt][1], bq[nt][2], bq[nt][3],
                       &Bs[wn + nt * 8 + (lane & 7)][kh + ((lane >> 3) << 3)]);

            #pragma unroll
            for (int ks = 0; ks < 2; ks++) {
                const int k = kh + ks * 16;
                uint32_t aq[4][4];
                #pragma unroll
                for (int mt = 0; mt < 4; mt++)
                    ldm_x4(aq[mt][0], aq[mt][1], aq[mt][2], aq[mt][3],
                           &As[wm + mt * 16 + (lane & 15)][k + ((lane >> 4) << 3)]);
                #pragma unroll
                for (int mt = 0; mt < 4; mt++)
                    #pragma unroll
                    for (int nt = 0; nt < 4; nt++)
                        mma_f16(acc[mt][nt][0], acc[mt][nt][1],
                                acc[mt][nt][2], acc[mt][nt][3],
                                aq[mt][0], aq[mt][1], aq[mt][2], aq[mt][3],
                                bq[nt][ks * 2], bq[nt][ks * 2 + 1]);
            }
        }
        __syncthreads();
    }

    #pragma unroll
    for (int mt = 0; mt < 4; mt++) {
        int gr0 = m0 + wm + mt * 16 + g;
        #pragma unroll
        for (int nt = 0; nt < 4; nt++) {
            int gc = col0 + wn + nt * 8 + tig * 2;
            if (gc + 1 >= NTOT) continue;
            if (gr0 < NNODES)
                *(__half2*)(C + (size_t)gr0 * NTOT + gc) =
                    __floats2half2_rn(acc[mt][nt][0], acc[mt][nt][1]);
            if (gr0 + 8 < NNODES)
                *(__half2*)(C + (size_t)(gr0 + 8) * NTOT + gc) =
                    __floats2half2_rn(acc[mt][nt][2], acc[mt][nt][3]);
        }
    }
}

// ================= CSR construction ==========================================
__global__ void zero_cnt_kernel() {
    int i = blockIdx.x * blockDim.x + threadIdx.x;
    if (i < BTOT) g_cnt[i] = 0;
}

__global__ void hist_kernel(const int* __restrict__ rows, int E) {
    const int d = blockIdx.y;
    int e = blockIdx.x * blockDim.x + threadIdx.x;
    if (e >= E) return;
    atomicAdd(&g_cnt[d * NNODES + rows[(size_t)d * E + e]], 1);
}

__global__ void scan1_kernel() {
    __shared__ int sh[1024];
    int i = blockIdx.x * 1024 + threadIdx.x;
    int v = (i < BTOT) ? g_cnt[i] : 0;
    sh[threadIdx.x] = v;
    __syncthreads();
    #pragma unroll
    for (int off = 1; off < 1024; off <<= 1) {
        int t = (threadIdx.x >= off) ? sh[threadIdx.x - off] : 0;
        __syncthreads();
        sh[threadIdx.x] += t;
        __syncthreads();
    }
    if (i < BTOT) g_rowptr[i] = sh[threadIdx.x] - v;
    if (threadIdx.x == 1023) g_bsum[blockIdx.x] = sh[1023];
}

__global__ void scan2_kernel() {
    __shared__ int sh[1024];
    int v = (threadIdx.x < SCAN_BLKS) ? g_bsum[threadIdx.x] : 0;
    sh[threadIdx.x] = v;
    __syncthreads();
    #pragma unroll
    for (int off = 1; off < 1024; off <<= 1) {
        int t = (threadIdx.x >= off) ? sh[threadIdx.x - off] : 0;
        __syncthreads();
        sh[threadIdx.x] += t;
        __syncthreads();
    }
    if (threadIdx.x < SCAN_BLKS) g_bsum[threadIdx.x] = sh[threadIdx.x] - v;
}

__global__ void scan3_kernel(int total) {
    int i = blockIdx.x * 1024 + threadIdx.x;
    if (i < BTOT) {
        g_rowptr[i] += g_bsum[blockIdx.x];
        g_cnt[i] = 0;
    }
    if (i == 0) g_rowptr[BTOT] = total;
}

__global__ void scatter_kernel(const int* __restrict__ rows,
                               const int* __restrict__ cols,
                               const float* __restrict__ vals, int E) {
    const int d = blockIdx.y;
    int e = blockIdx.x * blockDim.x + threadIdx.x;
    if (e >= E) return;
    size_t eo = (size_t)d * E + e;
    int bin = d * NNODES + rows[eo];
    int pos = g_rowptr[bin] + atomicAdd(&g_cnt[bin], 1);
    g_ecv[pos] = make_int2(cols[eo], __float_as_int(vals[eo]));
}

// ================= CSR SpMM layer 1 (8-edge unroll for MLP) ==================
__global__ void __launch_bounds__(256)
spmm1_csr_kernel(const __half* __restrict__ sup1, const float* __restrict__ b1,
                 __half* __restrict__ h1h) {
    const int d    = blockIdx.y;
    const int wid  = threadIdx.x >> 5;
    const int lane = threadIdx.x & 31;
    const int row  = blockIdx.x * 8 + wid;
    if (row >= NNODES) return;

    const int bin = d * NNODES + row;
    int j         = g_rowptr[bin];
    const int end = g_rowptr[bin + 1];
    const int off = d * NHID + lane * 2;

    float2 acc = make_float2(0.f, 0.f);
    for (; j + 7 < end; j += 8) {
        int2 cv[8];
        #pragma unroll
        for (int q = 0; q < 8; q++) cv[q] = g_ecv[j + q];
        float2 s[8];
        #pragma unroll
        for (int q = 0; q < 8; q++)
            s[q] = __half22float2(*(const __half2*)(sup1 + (size_t)cv[q].x * HCAT + off));
        #pragma unroll
        for (int q = 0; q < 8; q++) {
            float v = __int_as_float(cv[q].y);
            acc.x += v * s[q].x;
            acc.y += v * s[q].y;
        }
    }
    for (; j < end; j++) {
        int2 cv = g_ecv[j];
        float v = __int_as_float(cv.y);
        float2 sv = __half22float2(*(const __half2*)(sup1 + (size_t)cv.x * HCAT + off));
        acc.x += v * sv.x;
        acc.y += v * sv.y;
    }

    float2 b = *(const float2*)(b1 + off);
    acc.x = fmaxf(acc.x + b.x, 0.f);
    acc.y = fmaxf(acc.y + b.y, 0.f);
    *(__half2*)(h1h + (size_t)row * HCAT + off) = __floats2half2_rn(acc.x, acc.y);
}

// ================= fused CSR SpMM layer 2 + bias + relu + max-pool ===========
__global__ void __launch_bounds__(256)
spmm2_fused_kernel(const __half* __restrict__ sup2, const float* __restrict__ b2,
                   float* __restrict__ out) {
    __shared__ float sm[8][52];
    const int row  = blockIdx.x;
    const int wid  = threadIdx.x >> 5;
    const int lane = threadIdx.x & 31;
    const bool act = lane < 25;            // 25 lanes x float2 = 50 classes

    float2 wmax = make_float2(-1e30f, -1e30f);

    for (int d = wid; d < DIMB; d += 8) {
        const int bin = d * NNODES + row;
        int j         = g_rowptr[bin];
        const int end = g_rowptr[bin + 1];
        const int off = d * NC2 + lane * 2;

        float2 acc = make_float2(0.f, 0.f);
        for (; j + 7 < end; j += 8) {
            int2 cv[8];
            #pragma unroll
            for (int q = 0; q < 8; q++) cv[q] = g_ecv[j + q];
            if (act) {
                float2 s[8];
                #pragma unroll
                for (int q = 0; q < 8; q++)
                    s[q] = __half22float2(*(const __half2*)(sup2 + (size_t)cv[q].x * NW2 + off));
                #pragma unroll
                for (int q = 0; q < 8; q++) {
                    float v = __int_as_float(cv[q].y);
                    acc.x += v * s[q].x;
                    acc.y += v * s[q].y;
                }
            }
        }
        for (; j < end; j++) {
            int2 cv = g_ecv[j];
            if (act) {
                float v = __int_as_float(cv.y);
                float2 sv = __half22float2(*(const __half2*)(sup2 + (size_t)cv.x * NW2 + off));
                acc.x += v * sv.x;
                acc.y += v * sv.y;
            }
        }
        if (act) {
            float2 b = *(const float2*)(b2 + d * NCLASS + lane * 2);
            wmax.x = fmaxf(wmax.x, acc.x + b.x);
            wmax.y = fmaxf(wmax.y, acc.y + b.y);
        }
    }

    if (act) {
        sm[wid][lane * 2]     = wmax.x;
        sm[wid][lane * 2 + 1] = wmax.y;
    }
    __syncthreads();

    int c = threadIdx.x;
    if (c < NCLASS) {
        float m = 0.f;                      // relu folds into the max
        #pragma unroll
        for (int ww = 0; ww < 8; ww++) m = fmaxf(m, sm[ww][c]);
        out[(size_t)row * NCLASS + c] = m;
    }
}

// ================= launch ====================================================
extern "C" void kernel_launch(void* const* d_in, const int* in_sizes, int n_in,
                              void* d_out, int out_size) {
    const float* x        = (const float*)d_in[0];
    const int*   adj_rows = (const int*)d_in[1];
    const int*   adj_cols = (const int*)d_in[2];
    const float* adj_vals = (const float*)d_in[3];
    const float* W1       = (const float*)d_in[4];
    const float* b1       = (const float*)d_in[5];
    const float* W2       = (const float*)d_in[6];
    const float* b2       = (const float*)d_in[7];
    float*       out      = (float*)d_out;

    const int E = in_sizes[1] / DIMB;

    __half *p_xh, *p_w1h, *p_w2h, *p_h1h, *p_sup1, *p_sup2;
    cudaGetSymbolAddress((void**)&p_xh,   g_xh);
    cudaGetSymbolAddress((void**)&p_w1h,  g_w1h);
    cudaGetSymbolAddress((void**)&p_w2h,  g_w2h);
    cudaGetSymbolAddress((void**)&p_sup1, g_sup1);
    cudaGetSymbolAddress((void**)&p_h1h,  g_h1h);
    cudaGetSymbolAddress((void**)&p_sup2, g_sup2);

    const dim3 egrid((E + 255) / 256, DIMB);
    const int mTiles = (NNODES + 127) / 128;

    // Fork a side stream so the CSR build overlaps prep + GEMM1 in the
    // captured graph.
    cudaStream_t s2;
    cudaStreamCreateWithFlags(&s2, cudaStreamNonBlocking);
    cudaEvent_t eFork, eJoin;
    cudaEventCreateWithFlags(&eFork, cudaEventDisableTiming);
    cudaEventCreateWithFlags(&eJoin, cudaEventDisableTiming);

    cudaEventRecord(eFork, 0);
    cudaStreamWaitEvent(s2, eFork, 0);

    // --- branch A (s2): CSR build -------------------------------------------
    zero_cnt_kernel<<<(BTOT + 255) / 256, 256, 0, s2>>>();
    hist_kernel<<<egrid, 256, 0, s2>>>(adj_rows, E);
    scan1_kernel<<<SCAN_BLKS, 1024, 0, s2>>>();
    scan2_kernel<<<1, 1024, 0, s2>>>();
    scan3_kernel<<<SCAN_BLKS, 1024, 0, s2>>>(DIMB * E);
    scatter_kernel<<<egrid, 256, 0, s2>>>(adj_rows, adj_cols, adj_vals, E);
    cudaEventRecord(eJoin, s2);

    // --- branch B (main stream): prep + GEMM1 --------------------------------
    cvt_x_kernel<<<(NNODES * KPAD1 / 4 + 255) / 256, 256>>>(x, p_xh);
    repack1_kernel<<<(HCAT * KPAD1 + 255) / 256, 256>>>(W1, p_w1h);
    repack2_kernel<<<(NW2 * HCAT + 255) / 256, 256>>>(W2, p_w2h);
    h_mma_kernel<KPAD1, HCAT>
        <<<dim3((HCAT + 127) / 128, mTiles), 256>>>(p_xh, p_w1h, p_sup1);

    // --- join: spmm1 needs both GEMM1 output and the CSR ---------------------
    cudaStreamWaitEvent(0, eJoin, 0);

    spmm1_csr_kernel<<<dim3(NNODES / 8, DIMB), 256>>>(p_sup1, b1, p_h1h);

    h_mma_kernel<HCAT, NW2>
        <<<dim3((NW2 + 127) / 128, mTiles), 256>>>(p_h1h, p_w2h, p_sup2);
    spmm2_fused_kernel<<<NNODES, 256>>>(p_sup2, b2, out);
}